// round 12
// baseline (speedup 1.0000x reference)
#include <cuda_runtime.h>
#include <cstdint>

#define Nn 2048
#define Dd 1024
#define Hh 16
#define HD 64
#define NEMB 199
#define RAD 99

// ---------------- scratch (device globals; no allocation) ----------------
__device__ float g_q[Hh * Nn * HD];        // tf32 bits
__device__ float g_k[Hh * Nn * HD];        // tf32 bits, pre-scaled by 1/8
__device__ float g_v[Hh * Nn * HD];        // tf32 bits
__device__ float g_Et[Hh * 224 * HD];      // tf32 rel_emb, zero-padded to 224 rows
__device__ float g_ao[Nn * Dd];
__device__ uint32_t g_Ap[Nn * Dd];         // packed A frags (tf32 bits)
__device__ uint32_t g_Bp[3 * Dd * Dd];     // packed B frags (tf32 bits)

// ---------------- common helpers ------------------------------------------
__device__ __forceinline__ uint32_t f2tf(float f) {
    uint32_t u;
    asm("cvt.rna.tf32.f32 %0, %1;" : "=r"(u) : "f"(f));
    return u;
}
__device__ __forceinline__ float f2tff(float f) {
    return __uint_as_float(f2tf(f));
}
__device__ __forceinline__ uint32_t smem_u32(const void* p) {
    uint32_t a;
    asm("{ .reg .u64 t; cvta.to.shared.u64 t, %1; cvt.u32.u64 %0, t; }"
        : "=r"(a) : "l"(p));
    return a;
}
__device__ __forceinline__ void cp16(uint32_t dst, const void* src) {
    asm volatile("cp.async.cg.shared.global [%0], [%1], 16;" :: "r"(dst), "l"(src) : "memory");
}

#define MMA_TF32(d, a0, a1, a2, a3, b0, b1) \
    asm volatile( \
        "mma.sync.aligned.m16n8k8.row.col.f32.tf32.tf32.f32 " \
        "{%0,%1,%2,%3}, {%4,%5,%6,%7}, {%8,%9}, {%0,%1,%2,%3};" \
        : "+f"((d)[0]), "+f"((d)[1]), "+f"((d)[2]), "+f"((d)[3]) \
        : "r"(a0), "r"(a1), "r"(a2), "r"(a3), "r"(b0), "r"(b1))

// ---------------- pack kernels: fp32 -> fragment-ready tf32 ----------------
template <int SRCAO>
__global__ void __launch_bounds__(256) packA(const float* __restrict__ src,
                                             int rows, int K)
{
    const float* in = SRCAO ? (const float*)g_ao : src;
    int idx = blockIdx.x * 256 + threadIdx.x;
    int KS = K >> 3;
    int total = (rows >> 4) * KS * 32;
    if (idx >= total) return;
    int lane = idx & 31;
    int ks = (idx >> 5) % KS;
    int mt = (idx >> 5) / KS;
    int gid = lane >> 2, tig = lane & 3;
    int r0 = mt * 16 + gid, c0 = ks * 8 + tig;
    uint4 o;
    o.x = f2tf(in[(size_t)r0 * K + c0]);
    o.y = f2tf(in[(size_t)(r0 + 8) * K + c0]);
    o.z = f2tf(in[(size_t)r0 * K + c0 + 4]);
    o.w = f2tf(in[(size_t)(r0 + 8) * K + c0 + 4]);
    *(uint4*)&g_Ap[(size_t)idx * 4] = o;
}

__global__ void __launch_bounds__(256) packB(const float* __restrict__ src,
                                             int rowsB, int K)
{
    int idx = blockIdx.x * 256 + threadIdx.x;
    int KS = K >> 3;
    int total = (rowsB >> 3) * KS * 32;
    if (idx >= total) return;
    int lane = idx & 31;
    int ks = (idx >> 5) % KS;
    int nt = (idx >> 5) / KS;
    int gid = lane >> 2, tig = lane & 3;
    int n = nt * 8 + gid, c0 = ks * 8 + tig;
    uint2 o;
    o.x = f2tf(src[(size_t)n * K + c0]);
    o.y = f2tf(src[(size_t)n * K + c0 + 4]);
    *(uint2*)&g_Bp[(size_t)idx * 2] = o;
}

// tf32 rel_emb, zero-padded rows [NEMB, 224)
__global__ void __launch_bounds__(256) packE(const float* __restrict__ rel)
{
    int idx = blockIdx.x * 256 + threadIdx.x;
    if (idx >= Hh * 224 * HD) return;
    int d = idx & 63;
    int r = (idx >> 6) % 224;
    int h = idx / (224 * 64);
    float v = 0.f;
    if (r < NEMB) v = f2tff(rel[((size_t)h * NEMB + r) * HD + d]);
    g_Et[idx] = v;
}

// ---------------- tf32 mma.sync GEMM, 128x64 tile, 3 CTA/SM ---------------
// 3-stage cp.async; warp grid 4(m) x 2(n), warp tile 32x32.
#define GEMM_SMEM_BYTES 73728    // 3 stages x (16KB A + 8KB B)

template <int MODE>
__global__ void __launch_bounds__(256, 3) mma_gemm(
    const float* __restrict__ bias, float* __restrict__ out, int K)
{
    extern __shared__ __align__(16) uint32_t smem[];
    uint32_t* sAm = smem;                 // [3][4096]
    uint32_t* sBm = smem + 12288;         // [3][2048]
    const uint32_t sAu = smem_u32(sAm);
    const uint32_t sBu = smem_u32(sBm);

    const int t = threadIdx.x;
    const int KS = K >> 3;
    const int m0 = blockIdx.y * 128;
    const int n0 = blockIdx.x * 64;
    const int w = t >> 5, lane = t & 31;
    const int wy = w >> 1, wx = w & 1;      // 4 x 2 warp grid, warp tile 32x32
    const int gid = lane >> 2, tig = lane & 3;

    const uint32_t* Abase = g_Ap + (size_t)(blockIdx.y * 8) * KS * 128;
    const uint32_t* Bbase = g_Bp + (size_t)(blockIdx.x * 8) * KS * 64;

    float acc[2][4][4];
#pragma unroll
    for (int mi = 0; mi < 2; mi++)
#pragma unroll
        for (int ni = 0; ni < 4; ni++)
#pragma unroll
            for (int j = 0; j < 4; j++) acc[mi][ni][j] = 0.f;

    const int nc = K / 32;

    auto load_chunk = [&](int c, int s) {
        uint32_t ab = sAu + (uint32_t)s * 16384u;
        uint32_t bb = sBu + (uint32_t)s * 8192u;
#pragma unroll
        for (int q = 0; q < 4; q++) {
            int i4 = t + q * 256;                 // 0..1023
            int mt = i4 >> 7, rema = (i4 & 127) << 2;
            cp16(ab + (uint32_t)i4 * 16,
                 Abase + (size_t)mt * KS * 128 + c * 512 + rema);
        }
#pragma unroll
        for (int q = 0; q < 2; q++) {
            int i4 = t + q * 256;                 // 0..511
            int nt = i4 >> 6, remb = (i4 & 63) << 2;
            cp16(bb + (uint32_t)i4 * 16,
                 Bbase + (size_t)nt * KS * 64 + c * 256 + remb);
        }
    };

    load_chunk(0, 0);
    asm volatile("cp.async.commit_group;" ::: "memory");
    load_chunk(1, 1);
    asm volatile("cp.async.commit_group;" ::: "memory");

    for (int c = 0; c < nc; ++c) {
        int s = c - (c / 3) * 3;
        asm volatile("cp.async.wait_group 1;" ::: "memory");
        __syncthreads();
        if (c + 2 < nc) {
            int s2 = (c + 2) - ((c + 2) / 3) * 3;
            load_chunk(c + 2, s2);
            asm volatile("cp.async.commit_group;" ::: "memory");
        } else {
            asm volatile("cp.async.commit_group;" ::: "memory");
        }

        const uint32_t* As = sAm + s * 4096;
        const uint32_t* Bs = sBm + s * 2048;
#pragma unroll
        for (int ksp = 0; ksp < 4; ksp++) {
            uint4 af[2];
            uint2 bf[4];
#pragma unroll
            for (int mi = 0; mi < 2; mi++)
                af[mi] = *(const uint4*)&As[(((wy * 2 + mi) * 4 + ksp) << 7) + (lane << 2)];
#pragma unroll
            for (int ni = 0; ni < 4; ni++)
                bf[ni] = *(const uint2*)&Bs[(((wx * 4 + ni) * 4 + ksp) << 6) + (lane << 1)];
#pragma unroll
            for (int mi = 0; mi < 2; mi++)
#pragma unroll
                for (int ni = 0; ni < 4; ni++)
                    MMA_TF32(acc[mi][ni], af[mi].x, af[mi].y, af[mi].z, af[mi].w,
                             bf[ni].x, bf[ni].y);
        }
    }

#pragma unroll
    for (int mi = 0; mi < 2; mi++) {
        int r0 = m0 + wy * 32 + mi * 16 + gid;
#pragma unroll
        for (int ni = 0; ni < 4; ni++) {
            int feat = n0 + wx * 32 + ni * 8 + 2 * tig;
            float2 bb = *(const float2*)&bias[feat];
            if (MODE == 0) {
                int sec = feat >> 10, hm = feat & 1023;
                float* p = (sec == 0) ? g_q : ((sec == 1) ? g_k : g_v);
                float sc = (sec == 1) ? 0.125f : 1.0f;
                int h = hm >> 6, d = hm & 63;
                float2 v0 = make_float2(f2tff((acc[mi][ni][0] + bb.x) * sc),
                                        f2tff((acc[mi][ni][1] + bb.y) * sc));
                float2 v1 = make_float2(f2tff((acc[mi][ni][2] + bb.x) * sc),
                                        f2tff((acc[mi][ni][3] + bb.y) * sc));
                *(float2*)&p[((h * Nn + r0) << 6) + d] = v0;
                *(float2*)&p[((h * Nn + r0 + 8) << 6) + d] = v1;
            } else {
                float2 v0 = make_float2(acc[mi][ni][0] + bb.x, acc[mi][ni][1] + bb.y);
                float2 v1 = make_float2(acc[mi][ni][2] + bb.x, acc[mi][ni][3] + bb.y);
                *(float2*)&out[(size_t)r0 * Dd + feat] = v0;
                *(float2*)&out[(size_t)(r0 + 8) * Dd + feat] = v1;
            }
        }
    }
}

// ---------------- fused banded attention + pos logits, 64q/512t ----------
// cp.async everywhere; Spos held in regs, merged into band-relative S.
#define QT 64
#define BND 288
#define ERWS 224
#define BP 68
#define SSP2 244           // band-relative S pitch
#define SQ_F (QT * BP)                 // 4352
#define SE_F (ERWS * BP)               // 15232
#define SB_F (BND * BP)                // 19584
#define SS_F (QT * SSP2)               // 15616
#define ATTN_SMEM_BYTES ((SQ_F + SE_F + SB_F + SS_F) * 4)   // 219136

__global__ void __launch_bounds__(512) attn_kernel()
{
    extern __shared__ __align__(16) float sm[];
    float* sQ = sm;                    // [64][BP]
    float* sE = sm + SQ_F;             // [224][BP]
    float* sB = sm + SQ_F + SE_F;      // [288][BP]: K -> V
    float* sS = sm + SQ_F + SE_F + SB_F; // [64][SSP2] band-relative S/P
    const uint32_t sQu = smem_u32(sQ);
    const uint32_t sEu = smem_u32(sE);
    const uint32_t sBu = smem_u32(sB);

    const int h = blockIdx.y;
    const int i0 = blockIdx.x * QT;
    const int jlo = i0 - RAD;
    const int t = threadIdx.x;
    const int w = t >> 5, lane = t & 31;
    const int gid = lane >> 2, tig = lane & 3;
    const int mw = w & 3, nw = w >> 2;

    // ---- issue Q + E cp.async (group A) ----
    const float* Qg = g_q + ((size_t)(h * Nn + i0) << 6);
    for (int idx = t; idx < QT * 16; idx += 512) {
        int qi = idx >> 4, d4 = (idx & 15) << 2;
        cp16(sQu + (uint32_t)(qi * BP + d4) * 4, Qg + (qi << 6) + d4);
    }
    const float* Eg = g_Et + (size_t)h * ERWS * HD;
    for (int idx = t; idx < ERWS * 16; idx += 512) {
        int r = idx >> 4, d4 = (idx & 15) << 2;
        cp16(sEu + (uint32_t)(r * BP + d4) * 4, Eg + r * HD + d4);
    }
    asm volatile("cp.async.commit_group;" ::: "memory");

    // ---- issue K band cp.async (group B), zero-fill invalid rows ----
    for (int idx = t; idx < BND * 16; idx += 512) {
        int jj = idx >> 4, d4 = (idx & 15) << 2;
        int j = jlo + jj;
        if (j >= 0 && j < Nn)
            cp16(sBu + (uint32_t)(jj * BP + d4) * 4,
                 g_k + (((size_t)(h * Nn) + j) << 6) + d4);
        else
            *(float4*)&sB[jj * BP + d4] = make_float4(0.f, 0.f, 0.f, 0.f);
    }
    asm volatile("cp.async.commit_group;" ::: "memory");

    asm volatile("cp.async.wait_group 1;" ::: "memory");
    __syncthreads();

    // ---- Spos = Q @ E^T, accumulators kept in registers ----
    float pacc[7][4];
#pragma unroll
    for (int f = 0; f < 7; f++)
#pragma unroll
        for (int j = 0; j < 4; j++) pacc[f][j] = 0.f;
#pragma unroll
    for (int ks = 0; ks < 8; ks++) {
        int kb = ks * 8 + tig;
        uint32_t a0 = __float_as_uint(sQ[(mw * 16 + gid) * BP + kb]);
        uint32_t a1 = __float_as_uint(sQ[(mw * 16 + gid + 8) * BP + kb]);
        uint32_t a2 = __float_as_uint(sQ[(mw * 16 + gid) * BP + kb + 4]);
        uint32_t a3 = __float_as_uint(sQ[(mw * 16 + gid + 8) * BP + kb + 4]);
#pragma unroll
        for (int f = 0; f < 7; f++) {
            int nb = (nw * 7 + f) * 8;
            uint32_t b0 = __float_as_uint(sE[(nb + gid) * BP + kb]);
            uint32_t b1 = __float_as_uint(sE[(nb + gid) * BP + kb + 4]);
            MMA_TF32(pacc[f], a0, a1, a2, a3, b0, b1);
        }
    }

    asm volatile("cp.async.wait_group 0;" ::: "memory");
    __syncthreads();

    // ---- Sqk band-restricted -> store band-relative: local col = jj - 16mw --
    {
        float acc[7][4];
#pragma unroll
        for (int f = 0; f < 7; f++)
#pragma unroll
            for (int j = 0; j < 4; j++) acc[f][j] = 0.f;
#pragma unroll
        for (int ks = 0; ks < 8; ks++) {
            int kb = ks * 8 + tig;
            uint32_t a0 = __float_as_uint(sQ[(mw * 16 + gid) * BP + kb]);
            uint32_t a1 = __float_as_uint(sQ[(mw * 16 + gid + 8) * BP + kb]);
            uint32_t a2 = __float_as_uint(sQ[(mw * 16 + gid) * BP + kb + 4]);
            uint32_t a3 = __float_as_uint(sQ[(mw * 16 + gid + 8) * BP + kb + 4]);
#pragma unroll
            for (int f = 0; f < 7; f++) {
                int nb = (2 * mw + nw * 7 + f) * 8;
                uint32_t b0 = __float_as_uint(sB[(nb + gid) * BP + kb]);
                uint32_t b1 = __float_as_uint(sB[(nb + gid) * BP + kb + 4]);
                MMA_TF32(acc[f], a0, a1, a2, a3, b0, b1);
            }
        }
        int r0 = mw * 16 + gid;
#pragma unroll
        for (int f = 0; f < 7; f++) {
            int col = (nw * 7 + f) * 8 + 2 * tig;   // local = global - 16mw
            *(float2*)&sS[r0 * SSP2 + col] = make_float2(acc[f][0], acc[f][1]);
            *(float2*)&sS[(r0 + 8) * SSP2 + col] = make_float2(acc[f][2], acc[f][3]);
        }
    }
    __syncthreads();

    // ---- issue V band cp.async (overwrites sB) ----
    for (int idx = t; idx < BND * 16; idx += 512) {
        int jj = idx >> 4, d4 = (idx & 15) << 2;
        int j = jlo + jj;
        if (j >= 0 && j < Nn)
            cp16(sBu + (uint32_t)(jj * BP + d4) * 4,
                 g_v + (((size_t)(h * Nn) + j) << 6) + d4);
        else
            *(float4*)&sB[jj * BP + d4] = make_float4(0.f, 0.f, 0.f, 0.f);
    }
    asm volatile("cp.async.commit_group;" ::: "memory");

    // ---- merge pos into S (scalar: diagonal shift makes offsets odd) ----
    {
        int rl0 = gid, rl1 = gid + 8;          // local rows within m-tile mw
        int q0 = mw * 16 + gid, q1 = q0 + 8;   // tile rows
#pragma unroll
        for (int f = 0; f < 7; f++) {
            int r = (nw * 7 + f) * 8 + 2 * tig;
            float* p0 = &sS[q0 * SSP2 + rl0 + r];
            p0[0] += pacc[f][0];
            p0[1] += pacc[f][1];
            float* p1 = &sS[q1 * SSP2 + rl1 + r];
            p1[0] += pacc[f][2];
            p1[1] += pacc[f][3];
        }
    }
    __syncthreads();

    // ---- banded softmax, 4 rows/warp ILP; P written as tf32 ----
    {
        float v[4][7];
#pragma unroll
        for (int p = 0; p < 4; p++) {
            int qi = w * 4 + p;
            int ql = qi & 15;
            int i = i0 + qi;
#pragma unroll
            for (int u = 0; u < 7; u++) {
                int r = lane + u * 32;
                float val = -1e30f;
                if (r < NEMB) {
                    int j = i - RAD + r;
                    if (j >= 0 && j < Nn)
                        val = sS[qi * SSP2 + ql + r];
                }
                v[p][u] = val;
            }
        }
        float mx[4];
#pragma unroll
        for (int p = 0; p < 4; p++) {
            mx[p] = v[p][0];
#pragma unroll
            for (int u = 1; u < 7; u++) mx[p] = fmaxf(mx[p], v[p][u]);
        }
#pragma unroll
        for (int off = 16; off; off >>= 1)
#pragma unroll
            for (int p = 0; p < 4; p++)
                mx[p] = fmaxf(mx[p], __shfl_xor_sync(0xffffffffu, mx[p], off));
        float s[4] = {0.f, 0.f, 0.f, 0.f};
#pragma unroll
        for (int p = 0; p < 4; p++)
#pragma unroll
            for (int u = 0; u < 7; u++) {
                v[p][u] = (v[p][u] > -1e29f) ? __expf(v[p][u] - mx[p]) : 0.f;
                s[p] += v[p][u];
            }
#pragma unroll
        for (int off = 16; off; off >>= 1)
#pragma unroll
            for (int p = 0; p < 4; p++)
                s[p] += __shfl_xor_sync(0xffffffffu, s[p], off);
        float inv[4];
#pragma unroll
        for (int p = 0; p < 4; p++) inv[p] = 1.f / s[p];

        // zero cols [0,224), then write normalized P at band positions
#pragma unroll
        for (int p = 0; p < 4; p++) {
            int qi = w * 4 + p;
#pragma unroll
            for (int u = 0; u < 7; u++)
                sS[qi * SSP2 + lane + u * 32] = 0.f;
        }
        __syncwarp();
#pragma unroll
        for (int p = 0; p < 4; p++) {
            int qi = w * 4 + p;
            int ql = qi & 15;
#pragma unroll
            for (int u = 0; u < 7; u++) {
                int r = lane + u * 32;
                if (r < NEMB && v[p][u] != 0.f)
                    sS[qi * SSP2 + ql + r] = f2tff(v[p][u] * inv[p]);
            }
        }
    }
    asm volatile("cp.async.wait_group 0;" ::: "memory");
    __syncthreads();

    // ---- O = P @ V (band-relative): A cols [0,216), B rows 16mw + kb ----
    {
        float acc[2][4];
#pragma unroll
        for (int ff = 0; ff < 2; ff++)
#pragma unroll
            for (int j = 0; j < 4; j++) acc[ff][j] = 0.f;

#pragma unroll
        for (int ks = 0; ks < 27; ks++) {
            int kb = ks * 8 + tig;
            uint32_t a0 = __float_as_uint(sS[(mw * 16 + gid) * SSP2 + kb]);
            uint32_t a1 = __float_as_uint(sS[(mw * 16 + gid + 8) * SSP2 + kb]);
            uint32_t a2 = __float_as_uint(sS[(mw * 16 + gid) * SSP2 + kb + 4]);
            uint32_t a3 = __float_as_uint(sS[(mw * 16 + gid + 8) * SSP2 + kb + 4]);
            int vrow = mw * 16 + kb;
#pragma unroll
            for (int ff = 0; ff < 2; ff++) {
                int nd = (nw * 2 + ff) * 8 + gid;
                uint32_t b0 = __float_as_uint(sB[vrow * BP + nd]);
                uint32_t b1 = __float_as_uint(sB[(vrow + 4) * BP + nd]);
                MMA_TF32(acc[ff], a0, a1, a2, a3, b0, b1);
            }
        }
        int row = mw * 16 + gid;
#pragma unroll
        for (int ff = 0; ff < 2; ff++) {
            int dcol = h * 64 + (nw * 2 + ff) * 8 + 2 * tig;
            *(float2*)&g_ao[(size_t)(i0 + row) * Dd + dcol] =
                make_float2(acc[ff][0], acc[ff][1]);
            *(float2*)&g_ao[(size_t)(i0 + row + 8) * Dd + dcol] =
                make_float2(acc[ff][2], acc[ff][3]);
        }
    }
}

// ---------------- launcher ------------------------------------------------
extern "C" void kernel_launch(void* const* d_in, const int* in_sizes, int n_in,
                              void* d_out, int out_size)
{
    (void)in_sizes; (void)n_in; (void)out_size;
    const float* x      = (const float*)d_in[0];
    const float* qkv_w  = (const float*)d_in[1];
    const float* qkv_b  = (const float*)d_in[2];
    const float* proj_w = (const float*)d_in[3];
    const float* proj_b = (const float*)d_in[4];
    const float* rel    = (const float*)d_in[5];
    float* out = (float*)d_out;

    cudaFuncSetAttribute(mma_gemm<0>, cudaFuncAttributeMaxDynamicSharedMemorySize,
                         GEMM_SMEM_BYTES);
    cudaFuncSetAttribute(mma_gemm<1>, cudaFuncAttributeMaxDynamicSharedMemorySize,
                         GEMM_SMEM_BYTES);
    cudaFuncSetAttribute(attn_kernel, cudaFuncAttributeMaxDynamicSharedMemorySize,
                         ATTN_SMEM_BYTES);

    // 1) packs: x (A-frags), qkv_w (B-frags), rel_emb (tf32, padded)
    packA<0><<<(Nn / 16) * (Dd / 8) * 32 / 256, 256>>>(x, Nn, Dd);
    packB<<<(3 * Dd / 8) * (Dd / 8) * 32 / 256, 256>>>(qkv_w, 3 * Dd, Dd);
    packE<<<Hh * 224 * HD / 256, 256>>>(rel);
    // 2) QKV GEMM (128x64 tiles, 3 CTA/SM): scatter q / k(scaled) / v as tf32
    mma_gemm<0><<<dim3(3 * Dd / 64, Nn / 128), 256, GEMM_SMEM_BYTES>>>(qkv_b,
                                                                       nullptr, Dd);
    // 3) fused pos + banded attention -> g_ao
    attn_kernel<<<dim3(Nn / QT, Hh), 512, ATTN_SMEM_BYTES>>>();
    // 4) pack g_ao (A-frags) and proj_w (B-frags)
    packA<1><<<(Nn / 16) * (Dd / 8) * 32 / 256, 256>>>(nullptr, Nn, Dd);
    packB<<<(Dd / 8) * (Dd / 8) * 32 / 256, 256>>>(proj_w, Dd, Dd);
    // 5) output projection -> d_out
    mma_gemm<1><<<dim3(Dd / 64, Nn / 128), 256, GEMM_SMEM_BYTES>>>(proj_b, out, Dd);
}

// round 13
// speedup vs baseline: 1.0706x; 1.0706x over previous
#include <cuda_runtime.h>
#include <cstdint>

#define Nn 2048
#define Dd 1024
#define Hh 16
#define HD 64
#define NEMB 199
#define RAD 99

// ---------------- scratch (device globals; no allocation) ----------------
__device__ float g_q[Hh * Nn * HD];        // tf32 bits
__device__ float g_k[Hh * Nn * HD];        // tf32 bits, pre-scaled by 1/8
__device__ float g_v[Hh * Nn * HD];        // tf32 bits
__device__ float g_Et[Hh * 224 * HD];      // tf32 rel_emb, zero-padded to 224 rows
__device__ uint32_t g_Ap[Nn * Dd];         // packed A frags (tf32 bits)
__device__ uint32_t g_Bp[3 * Dd * Dd];     // packed B frags (tf32 bits)

// ---------------- common helpers ------------------------------------------
__device__ __forceinline__ uint32_t f2tf(float f) {
    uint32_t u;
    asm("cvt.rna.tf32.f32 %0, %1;" : "=r"(u) : "f"(f));
    return u;
}
__device__ __forceinline__ float f2tff(float f) {
    return __uint_as_float(f2tf(f));
}
__device__ __forceinline__ uint32_t smem_u32(const void* p) {
    uint32_t a;
    asm("{ .reg .u64 t; cvta.to.shared.u64 t, %1; cvt.u32.u64 %0, t; }"
        : "=r"(a) : "l"(p));
    return a;
}
__device__ __forceinline__ void cp16(uint32_t dst, const void* src) {
    asm volatile("cp.async.cg.shared.global [%0], [%1], 16;" :: "r"(dst), "l"(src) : "memory");
}

#define MMA_TF32(d, a0, a1, a2, a3, b0, b1) \
    asm volatile( \
        "mma.sync.aligned.m16n8k8.row.col.f32.tf32.tf32.f32 " \
        "{%0,%1,%2,%3}, {%4,%5,%6,%7}, {%8,%9}, {%0,%1,%2,%3};" \
        : "+f"((d)[0]), "+f"((d)[1]), "+f"((d)[2]), "+f"((d)[3]) \
        : "r"(a0), "r"(a1), "r"(a2), "r"(a3), "r"(b0), "r"(b1))

// ---------------- pack kernels: fp32 -> fragment-ready tf32 ----------------
__global__ void __launch_bounds__(256) packA(const float* __restrict__ src,
                                             int rows, int K)
{
    int idx = blockIdx.x * 256 + threadIdx.x;
    int KS = K >> 3;
    int total = (rows >> 4) * KS * 32;
    if (idx >= total) return;
    int lane = idx & 31;
    int ks = (idx >> 5) % KS;
    int mt = (idx >> 5) / KS;
    int gid = lane >> 2, tig = lane & 3;
    int r0 = mt * 16 + gid, c0 = ks * 8 + tig;
    uint4 o;
    o.x = f2tf(src[(size_t)r0 * K + c0]);
    o.y = f2tf(src[(size_t)(r0 + 8) * K + c0]);
    o.z = f2tf(src[(size_t)r0 * K + c0 + 4]);
    o.w = f2tf(src[(size_t)(r0 + 8) * K + c0 + 4]);
    *(uint4*)&g_Ap[(size_t)idx * 4] = o;
}

__global__ void __launch_bounds__(256) packB(const float* __restrict__ src,
                                             int rowsB, int K)
{
    int idx = blockIdx.x * 256 + threadIdx.x;
    int KS = K >> 3;
    int total = (rowsB >> 3) * KS * 32;
    if (idx >= total) return;
    int lane = idx & 31;
    int ks = (idx >> 5) % KS;
    int nt = (idx >> 5) / KS;
    int gid = lane >> 2, tig = lane & 3;
    int n = nt * 8 + gid, c0 = ks * 8 + tig;
    uint2 o;
    o.x = f2tf(src[(size_t)n * K + c0]);
    o.y = f2tf(src[(size_t)n * K + c0 + 4]);
    *(uint2*)&g_Bp[(size_t)idx * 2] = o;
}

// tf32 rel_emb, zero-padded rows [NEMB, 224)
__global__ void __launch_bounds__(256) packE(const float* __restrict__ rel)
{
    int idx = blockIdx.x * 256 + threadIdx.x;
    if (idx >= Hh * 224 * HD) return;
    int d = idx & 63;
    int r = (idx >> 6) % 224;
    int h = idx / (224 * 64);
    float v = 0.f;
    if (r < NEMB) v = f2tff(rel[((size_t)h * NEMB + r) * HD + d]);
    g_Et[idx] = v;
}

// ---------------- tf32 mma.sync GEMM, 3-stage cp.async (R11 config) -------
#define GEMM_SMEM_BYTES 98304

template <int MODE>
__global__ void __launch_bounds__(256, 2) mma_gemm(
    const float* __restrict__ bias, float* __restrict__ out, int K)
{
    extern __shared__ __align__(16) uint32_t smem[];
    uint32_t* sAm = smem;
    uint32_t* sBm = smem + 12288;
    const uint32_t sAu = smem_u32(sAm);
    const uint32_t sBu = smem_u32(sBm);

    const int t = threadIdx.x;
    const int KS = K >> 3;
    const int m0 = blockIdx.y * 128;
    const int n0 = blockIdx.x * 128;
    const int w = t >> 5, lane = t & 31;
    const int wy = w >> 2, wx = w & 3;
    const int gid = lane >> 2, tig = lane & 3;

    const uint32_t* Abase = g_Ap + (size_t)(blockIdx.y * 8) * KS * 128;
    const uint32_t* Bbase = g_Bp + (size_t)(blockIdx.x * 16) * KS * 64;

    float acc[4][4][4];
#pragma unroll
    for (int mi = 0; mi < 4; mi++)
#pragma unroll
        for (int ni = 0; ni < 4; ni++)
#pragma unroll
            for (int j = 0; j < 4; j++) acc[mi][ni][j] = 0.f;

    const int nc = K / 32;

    auto load_chunk = [&](int c, int s) {
        uint32_t ab = sAu + (uint32_t)s * 16384u;
        uint32_t bb = sBu + (uint32_t)s * 16384u;
#pragma unroll
        for (int q = 0; q < 4; q++) {
            int i4 = t + q * 256;
            int mt = i4 >> 7, rema = (i4 & 127) << 2;
            cp16(ab + (uint32_t)i4 * 16,
                 Abase + (size_t)mt * KS * 128 + c * 512 + rema);
            int nt = i4 >> 6, remb = (i4 & 63) << 2;
            cp16(bb + (uint32_t)i4 * 16,
                 Bbase + (size_t)nt * KS * 64 + c * 256 + remb);
        }
    };

    load_chunk(0, 0);
    asm volatile("cp.async.commit_group;" ::: "memory");
    load_chunk(1, 1);
    asm volatile("cp.async.commit_group;" ::: "memory");

    for (int c = 0; c < nc; ++c) {
        int s = c - (c / 3) * 3;
        asm volatile("cp.async.wait_group 1;" ::: "memory");
        __syncthreads();
        if (c + 2 < nc) {
            int s2 = (c + 2) - ((c + 2) / 3) * 3;
            load_chunk(c + 2, s2);
            asm volatile("cp.async.commit_group;" ::: "memory");
        } else {
            asm volatile("cp.async.commit_group;" ::: "memory");
        }

        const uint32_t* As = sAm + s * 4096;
        const uint32_t* Bs = sBm + s * 4096;
#pragma unroll
        for (int ksp = 0; ksp < 4; ksp++) {
            uint4 af[4];
            uint2 bf[4];
#pragma unroll
            for (int mi = 0; mi < 4; mi++)
                af[mi] = *(const uint4*)&As[(((wy * 4 + mi) * 4 + ksp) << 7) + (lane << 2)];
#pragma unroll
            for (int ni = 0; ni < 4; ni++)
                bf[ni] = *(const uint2*)&Bs[(((wx * 4 + ni) * 4 + ksp) << 6) + (lane << 1)];
#pragma unroll
            for (int mi = 0; mi < 4; mi++)
#pragma unroll
                for (int ni = 0; ni < 4; ni++)
                    MMA_TF32(acc[mi][ni], af[mi].x, af[mi].y, af[mi].z, af[mi].w,
                             bf[ni].x, bf[ni].y);
        }
    }

#pragma unroll
    for (int mi = 0; mi < 4; mi++) {
        int r0 = m0 + wy * 64 + mi * 16 + gid;
#pragma unroll
        for (int ni = 0; ni < 4; ni++) {
            int feat = n0 + wx * 32 + ni * 8 + 2 * tig;
            float2 bb = *(const float2*)&bias[feat];
            if (MODE == 0) {
                int sec = feat >> 10, hm = feat & 1023;
                float* p = (sec == 0) ? g_q : ((sec == 1) ? g_k : g_v);
                float sc = (sec == 1) ? 0.125f : 1.0f;
                int h = hm >> 6, d = hm & 63;
                float2 v0 = make_float2(f2tff((acc[mi][ni][0] + bb.x) * sc),
                                        f2tff((acc[mi][ni][1] + bb.y) * sc));
                float2 v1 = make_float2(f2tff((acc[mi][ni][2] + bb.x) * sc),
                                        f2tff((acc[mi][ni][3] + bb.y) * sc));
                *(float2*)&p[((h * Nn + r0) << 6) + d] = v0;
                *(float2*)&p[((h * Nn + r0 + 8) << 6) + d] = v1;
            } else {
                float2 v0 = make_float2(acc[mi][ni][0] + bb.x, acc[mi][ni][1] + bb.y);
                float2 v1 = make_float2(acc[mi][ni][2] + bb.x, acc[mi][ni][3] + bb.y);
                *(float2*)&out[(size_t)r0 * Dd + feat] = v0;
                *(float2*)&out[(size_t)(r0 + 8) * Dd + feat] = v1;
            }
        }
    }
}

// ---------------- fused banded attention + pos logits, 64q/512t ----------
// cp.async fills; Spos in regs merged into band-relative S; epilogue writes
// A-fragment-packed tf32 (g_Ap) directly -- no g_ao, no packA<1>.
#define QT 64
#define BND 288
#define ERWS 224
#define BP 68
#define SSP2 244           // band-relative S pitch
#define SQ_F (QT * BP)                 // 4352
#define SE_F (ERWS * BP)               // 15232
#define SB_F (BND * BP)                // 19584
#define SS_F (QT * SSP2)               // 15616
#define ATTN_SMEM_BYTES ((SQ_F + SE_F + SB_F + SS_F) * 4)   // 219136

// store one fp32 value as tf32 into the packed A-frag layout (KS=128)
__device__ __forceinline__ void store_afrag(int R, int C, float v) {
    int mt = R >> 4, ks = C >> 3;
    int lane = ((R & 7) << 2) + (C & 3);
    int slot = ((R & 15) >> 3) + (((C & 7) >> 2) << 1);
    g_Ap[((((size_t)mt * 128 + ks) << 5) + lane) * 4 + slot] = f2tf(v);
}

__global__ void __launch_bounds__(512) attn_kernel()
{
    extern __shared__ __align__(16) float sm[];
    float* sQ = sm;                    // [64][BP]
    float* sE = sm + SQ_F;             // [224][BP]
    float* sB = sm + SQ_F + SE_F;      // [288][BP]: K -> V
    float* sS = sm + SQ_F + SE_F + SB_F; // [64][SSP2] band-relative S/P
    const uint32_t sQu = smem_u32(sQ);
    const uint32_t sEu = smem_u32(sE);
    const uint32_t sBu = smem_u32(sB);

    const int h = blockIdx.y;
    const int i0 = blockIdx.x * QT;
    const int jlo = i0 - RAD;
    const int t = threadIdx.x;
    const int w = t >> 5, lane = t & 31;
    const int gid = lane >> 2, tig = lane & 3;
    const int mw = w & 3, nw = w >> 2;

    // ---- issue Q + E cp.async (group A) ----
    const float* Qg = g_q + ((size_t)(h * Nn + i0) << 6);
    for (int idx = t; idx < QT * 16; idx += 512) {
        int qi = idx >> 4, d4 = (idx & 15) << 2;
        cp16(sQu + (uint32_t)(qi * BP + d4) * 4, Qg + (qi << 6) + d4);
    }
    const float* Eg = g_Et + (size_t)h * ERWS * HD;
    for (int idx = t; idx < ERWS * 16; idx += 512) {
        int r = idx >> 4, d4 = (idx & 15) << 2;
        cp16(sEu + (uint32_t)(r * BP + d4) * 4, Eg + r * HD + d4);
    }
    asm volatile("cp.async.commit_group;" ::: "memory");

    // ---- issue K band cp.async (group B), zero-fill invalid rows ----
    for (int idx = t; idx < BND * 16; idx += 512) {
        int jj = idx >> 4, d4 = (idx & 15) << 2;
        int j = jlo + jj;
        if (j >= 0 && j < Nn)
            cp16(sBu + (uint32_t)(jj * BP + d4) * 4,
                 g_k + (((size_t)(h * Nn) + j) << 6) + d4);
        else
            *(float4*)&sB[jj * BP + d4] = make_float4(0.f, 0.f, 0.f, 0.f);
    }
    asm volatile("cp.async.commit_group;" ::: "memory");

    asm volatile("cp.async.wait_group 1;" ::: "memory");
    __syncthreads();

    // ---- Spos = Q @ E^T, accumulators kept in registers ----
    float pacc[7][4];
#pragma unroll
    for (int f = 0; f < 7; f++)
#pragma unroll
        for (int j = 0; j < 4; j++) pacc[f][j] = 0.f;
#pragma unroll
    for (int ks = 0; ks < 8; ks++) {
        int kb = ks * 8 + tig;
        uint32_t a0 = __float_as_uint(sQ[(mw * 16 + gid) * BP + kb]);
        uint32_t a1 = __float_as_uint(sQ[(mw * 16 + gid + 8) * BP + kb]);
        uint32_t a2 = __float_as_uint(sQ[(mw * 16 + gid) * BP + kb + 4]);
        uint32_t a3 = __float_as_uint(sQ[(mw * 16 + gid + 8) * BP + kb + 4]);
#pragma unroll
        for (int f = 0; f < 7; f++) {
            int nb = (nw * 7 + f) * 8;
            uint32_t b0 = __float_as_uint(sE[(nb + gid) * BP + kb]);
            uint32_t b1 = __float_as_uint(sE[(nb + gid) * BP + kb + 4]);
            MMA_TF32(pacc[f], a0, a1, a2, a3, b0, b1);
        }
    }

    asm volatile("cp.async.wait_group 0;" ::: "memory");
    __syncthreads();

    // ---- Sqk band-restricted -> store band-relative: local col = jj - 16mw --
    {
        float acc[7][4];
#pragma unroll
        for (int f = 0; f < 7; f++)
#pragma unroll
            for (int j = 0; j < 4; j++) acc[f][j] = 0.f;
#pragma unroll
        for (int ks = 0; ks < 8; ks++) {
            int kb = ks * 8 + tig;
            uint32_t a0 = __float_as_uint(sQ[(mw * 16 + gid) * BP + kb]);
            uint32_t a1 = __float_as_uint(sQ[(mw * 16 + gid + 8) * BP + kb]);
            uint32_t a2 = __float_as_uint(sQ[(mw * 16 + gid) * BP + kb + 4]);
            uint32_t a3 = __float_as_uint(sQ[(mw * 16 + gid + 8) * BP + kb + 4]);
#pragma unroll
            for (int f = 0; f < 7; f++) {
                int nb = (2 * mw + nw * 7 + f) * 8;
                uint32_t b0 = __float_as_uint(sB[(nb + gid) * BP + kb]);
                uint32_t b1 = __float_as_uint(sB[(nb + gid) * BP + kb + 4]);
                MMA_TF32(acc[f], a0, a1, a2, a3, b0, b1);
            }
        }
        int r0 = mw * 16 + gid;
#pragma unroll
        for (int f = 0; f < 7; f++) {
            int col = (nw * 7 + f) * 8 + 2 * tig;   // local = global - 16mw
            *(float2*)&sS[r0 * SSP2 + col] = make_float2(acc[f][0], acc[f][1]);
            *(float2*)&sS[(r0 + 8) * SSP2 + col] = make_float2(acc[f][2], acc[f][3]);
        }
    }
    __syncthreads();

    // ---- issue V band cp.async (overwrites sB) ----
    for (int idx = t; idx < BND * 16; idx += 512) {
        int jj = idx >> 4, d4 = (idx & 15) << 2;
        int j = jlo + jj;
        if (j >= 0 && j < Nn)
            cp16(sBu + (uint32_t)(jj * BP + d4) * 4,
                 g_v + (((size_t)(h * Nn) + j) << 6) + d4);
        else
            *(float4*)&sB[jj * BP + d4] = make_float4(0.f, 0.f, 0.f, 0.f);
    }
    asm volatile("cp.async.commit_group;" ::: "memory");

    // ---- merge pos into S (scalar: diagonal shift makes offsets odd) ----
    {
        int rl0 = gid, rl1 = gid + 8;
        int q0 = mw * 16 + gid, q1 = q0 + 8;
#pragma unroll
        for (int f = 0; f < 7; f++) {
            int r = (nw * 7 + f) * 8 + 2 * tig;
            float* p0 = &sS[q0 * SSP2 + rl0 + r];
            p0[0] += pacc[f][0];
            p0[1] += pacc[f][1];
            float* p1 = &sS[q1 * SSP2 + rl1 + r];
            p1[0] += pacc[f][2];
            p1[1] += pacc[f][3];
        }
    }
    __syncthreads();

    // ---- banded softmax, 4 rows/warp ILP; P written as tf32 ----
    {
        float v[4][7];
#pragma unroll
        for (int p = 0; p < 4; p++) {
            int qi = w * 4 + p;
            int ql = qi & 15;
            int i = i0 + qi;
#pragma unroll
            for (int u = 0; u < 7; u++) {
                int r = lane + u * 32;
                float val = -1e30f;
                if (r < NEMB) {
                    int j = i - RAD + r;
                    if (j >= 0 && j < Nn)
                        val = sS[qi * SSP2 + ql + r];
                }
                v[p][u] = val;
            }
        }
        float mx[4];
#pragma unroll
        for (int p = 0; p < 4; p++) {
            mx[p] = v[p][0];
#pragma unroll
            for (int u = 1; u < 7; u++) mx[p] = fmaxf(mx[p], v[p][u]);
        }
#pragma unroll
        for (int off = 16; off; off >>= 1)
#pragma unroll
            for (int p = 0; p < 4; p++)
                mx[p] = fmaxf(mx[p], __shfl_xor_sync(0xffffffffu, mx[p], off));
        float s[4] = {0.f, 0.f, 0.f, 0.f};
#pragma unroll
        for (int p = 0; p < 4; p++)
#pragma unroll
            for (int u = 0; u < 7; u++) {
                v[p][u] = (v[p][u] > -1e29f) ? __expf(v[p][u] - mx[p]) : 0.f;
                s[p] += v[p][u];
            }
#pragma unroll
        for (int off = 16; off; off >>= 1)
#pragma unroll
            for (int p = 0; p < 4; p++)
                s[p] += __shfl_xor_sync(0xffffffffu, s[p], off);
        float inv[4];
#pragma unroll
        for (int p = 0; p < 4; p++) inv[p] = 1.f / s[p];

#pragma unroll
        for (int p = 0; p < 4; p++) {
            int qi = w * 4 + p;
#pragma unroll
            for (int u = 0; u < 7; u++)
                sS[qi * SSP2 + lane + u * 32] = 0.f;
        }
        __syncwarp();
#pragma unroll
        for (int p = 0; p < 4; p++) {
            int qi = w * 4 + p;
            int ql = qi & 15;
#pragma unroll
            for (int u = 0; u < 7; u++) {
                int r = lane + u * 32;
                if (r < NEMB && v[p][u] != 0.f)
                    sS[qi * SSP2 + ql + r] = f2tff(v[p][u] * inv[p]);
            }
        }
    }
    asm volatile("cp.async.wait_group 0;" ::: "memory");
    __syncthreads();

    // ---- O = P @ V (band-relative); epilogue writes g_Ap frags directly ----
    {
        float acc[2][4];
#pragma unroll
        for (int ff = 0; ff < 2; ff++)
#pragma unroll
            for (int j = 0; j < 4; j++) acc[ff][j] = 0.f;

#pragma unroll
        for (int ks = 0; ks < 27; ks++) {
            int kb = ks * 8 + tig;
            uint32_t a0 = __float_as_uint(sS[(mw * 16 + gid) * SSP2 + kb]);
            uint32_t a1 = __float_as_uint(sS[(mw * 16 + gid + 8) * SSP2 + kb]);
            uint32_t a2 = __float_as_uint(sS[(mw * 16 + gid) * SSP2 + kb + 4]);
            uint32_t a3 = __float_as_uint(sS[(mw * 16 + gid + 8) * SSP2 + kb + 4]);
            int vrow = mw * 16 + kb;
#pragma unroll
            for (int ff = 0; ff < 2; ff++) {
                int nd = (nw * 2 + ff) * 8 + gid;
                uint32_t b0 = __float_as_uint(sB[vrow * BP + nd]);
                uint32_t b1 = __float_as_uint(sB[(vrow + 4) * BP + nd]);
                MMA_TF32(acc[ff], a0, a1, a2, a3, b0, b1);
            }
        }
        int R0 = i0 + mw * 16 + gid;
        int R1 = R0 + 8;
#pragma unroll
        for (int ff = 0; ff < 2; ff++) {
            int C = h * 64 + (nw * 2 + ff) * 8 + 2 * tig;
            store_afrag(R0, C,     acc[ff][0]);
            store_afrag(R0, C + 1, acc[ff][1]);
            store_afrag(R1, C,     acc[ff][2]);
            store_afrag(R1, C + 1, acc[ff][3]);
        }
    }
}

// ---------------- launcher ------------------------------------------------
extern "C" void kernel_launch(void* const* d_in, const int* in_sizes, int n_in,
                              void* d_out, int out_size)
{
    (void)in_sizes; (void)n_in; (void)out_size;
    const float* x      = (const float*)d_in[0];
    const float* qkv_w  = (const float*)d_in[1];
    const float* qkv_b  = (const float*)d_in[2];
    const float* proj_w = (const float*)d_in[3];
    const float* proj_b = (const float*)d_in[4];
    const float* rel    = (const float*)d_in[5];
    float* out = (float*)d_out;

    cudaFuncSetAttribute(mma_gemm<0>, cudaFuncAttributeMaxDynamicSharedMemorySize,
                         GEMM_SMEM_BYTES);
    cudaFuncSetAttribute(mma_gemm<1>, cudaFuncAttributeMaxDynamicSharedMemorySize,
                         GEMM_SMEM_BYTES);
    cudaFuncSetAttribute(attn_kernel, cudaFuncAttributeMaxDynamicSharedMemorySize,
                         ATTN_SMEM_BYTES);

    // 1) packs: x (A-frags), qkv_w (B-frags), rel_emb (tf32, padded)
    packA<<<(Nn / 16) * (Dd / 8) * 32 / 256, 256>>>(x, Nn, Dd);
    packB<<<(3 * Dd / 8) * (Dd / 8) * 32 / 256, 256>>>(qkv_w, 3 * Dd, Dd);
    packE<<<Hh * 224 * HD / 256, 256>>>(rel);
    // 2) QKV GEMM (128x128, 2 CTA/SM): scatter q / k(scaled) / v as tf32
    mma_gemm<0><<<dim3(3 * Dd / 128, Nn / 128), 256, GEMM_SMEM_BYTES>>>(qkv_b,
                                                                        nullptr, Dd);
    // 3) fused pos + banded attention -> g_Ap (A-frags, fused pack)
    attn_kernel<<<dim3(Nn / QT, Hh), 512, ATTN_SMEM_BYTES>>>();
    // 4) pack proj_w (B-frags)
    packB<<<(Dd / 8) * (Dd / 8) * 32 / 256, 256>>>(proj_w, Dd, Dd);
    // 5) output projection -> d_out
    mma_gemm<1><<<dim3(Dd / 128, Nn / 128), 256, GEMM_SMEM_BYTES>>>(proj_b, out, Dd);
}

// round 14
// speedup vs baseline: 1.4315x; 1.3371x over previous
#include <cuda_runtime.h>
#include <cuda_fp16.h>
#include <cstdint>

#define Nn 2048
#define Dd 1024
#define Hh 16
#define HD 64
#define NEMB 199
#define RAD 99

// ---------------- scratch (device globals; no allocation) ----------------
__device__ float g_q[Hh * Nn * HD];        // tf32 bits (attn operands)
__device__ float g_k[Hh * Nn * HD];        // tf32 bits, pre-scaled by 1/8
__device__ float g_v[Hh * Nn * HD];        // tf32 bits
__device__ float g_Et[Hh * 224 * HD];      // tf32 rel_emb, zero-padded
__device__ uint32_t g_Ap[Nn * Dd / 2];     // packed fp16 A frags
__device__ uint32_t g_Bp[3 * Dd * Dd / 2]; // packed fp16 B frags

// ---------------- common helpers ------------------------------------------
__device__ __forceinline__ uint32_t f2tf(float f) {
    uint32_t u;
    asm("cvt.rna.tf32.f32 %0, %1;" : "=r"(u) : "f"(f));
    return u;
}
__device__ __forceinline__ float f2tff(float f) {
    return __uint_as_float(f2tf(f));
}
__device__ __forceinline__ uint32_t f2h2(float a, float b) {
    __half2 h = __floats2half2_rn(a, b);
    return *(uint32_t*)&h;
}
__device__ __forceinline__ uint32_t smem_u32(const void* p) {
    uint32_t a;
    asm("{ .reg .u64 t; cvta.to.shared.u64 t, %1; cvt.u32.u64 %0, t; }"
        : "=r"(a) : "l"(p));
    return a;
}
__device__ __forceinline__ void cp16(uint32_t dst, const void* src) {
    asm volatile("cp.async.cg.shared.global [%0], [%1], 16;" :: "r"(dst), "l"(src) : "memory");
}

#define MMA_TF32(d, a0, a1, a2, a3, b0, b1) \
    asm volatile( \
        "mma.sync.aligned.m16n8k8.row.col.f32.tf32.tf32.f32 " \
        "{%0,%1,%2,%3}, {%4,%5,%6,%7}, {%8,%9}, {%0,%1,%2,%3};" \
        : "+f"((d)[0]), "+f"((d)[1]), "+f"((d)[2]), "+f"((d)[3]) \
        : "r"(a0), "r"(a1), "r"(a2), "r"(a3), "r"(b0), "r"(b1))

#define MMA_F16(d, a0, a1, a2, a3, b0, b1) \
    asm volatile( \
        "mma.sync.aligned.m16n8k16.row.col.f32.f16.f16.f32 " \
        "{%0,%1,%2,%3}, {%4,%5,%6,%7}, {%8,%9}, {%0,%1,%2,%3};" \
        : "+f"((d)[0]), "+f"((d)[1]), "+f"((d)[2]), "+f"((d)[3]) \
        : "r"(a0), "r"(a1), "r"(a2), "r"(a3), "r"(b0), "r"(b1))

// ---------------- pack kernels: fp32 -> fp16 fragment layouts --------------
// A-frag m16n8k16: per lane 4 uint32 (fp16x2): a0=(r,c0..c0+1) a1=(r+8,..)
// a2=(r,c0+8..9) a3=(r+8,c0+8..9); c0 = ks16*16 + 2*tig.
__global__ void __launch_bounds__(256) packA(const float* __restrict__ src,
                                             int rows, int K)
{
    int idx = blockIdx.x * 256 + threadIdx.x;
    int KS16 = K >> 4;
    int total = (rows >> 4) * KS16 * 32;
    if (idx >= total) return;
    int lane = idx & 31;
    int ks = (idx >> 5) % KS16;
    int mt = (idx >> 5) / KS16;
    int gid = lane >> 2, tig = lane & 3;
    int r0 = mt * 16 + gid, c0 = ks * 16 + 2 * tig;
    const float* p0 = src + (size_t)r0 * K + c0;
    const float* p1 = src + (size_t)(r0 + 8) * K + c0;
    uint4 o;
    o.x = f2h2(p0[0], p0[1]);
    o.y = f2h2(p1[0], p1[1]);
    o.z = f2h2(p0[8], p0[9]);
    o.w = f2h2(p1[8], p1[9]);
    *(uint4*)&g_Ap[(size_t)idx * 4] = o;
}

// B-frag k16n8: per lane 2 uint32: b0=(k=2tig..+1, n) b1=(k=2tig+8..+9, n)
__global__ void __launch_bounds__(256) packB(const float* __restrict__ src,
                                             int rowsB, int K)
{
    int idx = blockIdx.x * 256 + threadIdx.x;
    int KS16 = K >> 4;
    int total = (rowsB >> 3) * KS16 * 32;
    if (idx >= total) return;
    int lane = idx & 31;
    int ks = (idx >> 5) % KS16;
    int nt = (idx >> 5) / KS16;
    int gid = lane >> 2, tig = lane & 3;
    int n = nt * 8 + gid, c0 = ks * 16 + 2 * tig;
    const float* p = src + (size_t)n * K + c0;
    uint2 o;
    o.x = f2h2(p[0], p[1]);
    o.y = f2h2(p[8], p[9]);
    *(uint2*)&g_Bp[(size_t)idx * 2] = o;
}

// tf32 rel_emb, zero-padded rows [NEMB, 224)
__global__ void __launch_bounds__(256) packE(const float* __restrict__ rel)
{
    int idx = blockIdx.x * 256 + threadIdx.x;
    if (idx >= Hh * 224 * HD) return;
    int d = idx & 63;
    int r = (idx >> 6) % 224;
    int h = idx / (224 * 64);
    float v = 0.f;
    if (r < NEMB) v = f2tff(rel[((size_t)h * NEMB + r) * HD + d]);
    g_Et[idx] = v;
}

// ---------------- fp16 mma.sync GEMM, 128x128 tile, 3-stage cp.async ------
#define GEMM_SMEM_BYTES 49152    // 3 stages x (8KB A + 8KB B)

template <int MODE>
__global__ void __launch_bounds__(256, 2) mma_gemm(
    const float* __restrict__ bias, float* __restrict__ out, int K)
{
    extern __shared__ __align__(16) uint32_t smem[];
    uint32_t* sAm = smem;                 // [3][2048]
    uint32_t* sBm = smem + 6144;          // [3][2048]
    const uint32_t sAu = smem_u32(sAm);
    const uint32_t sBu = smem_u32(sBm);

    const int t = threadIdx.x;
    const int KS16 = K >> 4;
    const int m0 = blockIdx.y * 128;
    const int n0 = blockIdx.x * 128;
    const int w = t >> 5, lane = t & 31;
    const int wy = w >> 2, wx = w & 3;
    const int gid = lane >> 2, tig = lane & 3;

    const uint32_t* Abase = g_Ap + (size_t)(blockIdx.y * 8) * KS16 * 128;
    const uint32_t* Bbase = g_Bp + (size_t)(blockIdx.x * 16) * KS16 * 64;

    float acc[4][4][4];
#pragma unroll
    for (int mi = 0; mi < 4; mi++)
#pragma unroll
        for (int ni = 0; ni < 4; ni++)
#pragma unroll
            for (int j = 0; j < 4; j++) acc[mi][ni][j] = 0.f;

    const int nc = K / 32;   // chunk = 2 k16-slices

    auto load_chunk = [&](int c, int s) {
        uint32_t ab = sAu + (uint32_t)s * 8192u;
        uint32_t bb = sBu + (uint32_t)s * 8192u;
#pragma unroll
        for (int q = 0; q < 2; q++) {
            int i4 = t + q * 256;                   // 0..511
            int mt = i4 >> 6, rema = (i4 & 63) << 2;
            cp16(ab + (uint32_t)i4 * 16,
                 Abase + (size_t)mt * KS16 * 128 + c * 256 + rema);
            int nt = i4 >> 5, remb = (i4 & 31) << 2;
            cp16(bb + (uint32_t)i4 * 16,
                 Bbase + (size_t)nt * KS16 * 64 + c * 128 + remb);
        }
    };

    load_chunk(0, 0);
    asm volatile("cp.async.commit_group;" ::: "memory");
    load_chunk(1, 1);
    asm volatile("cp.async.commit_group;" ::: "memory");

    for (int c = 0; c < nc; ++c) {
        int s = c - (c / 3) * 3;
        asm volatile("cp.async.wait_group 1;" ::: "memory");
        __syncthreads();
        if (c + 2 < nc) {
            int s2 = (c + 2) - ((c + 2) / 3) * 3;
            load_chunk(c + 2, s2);
            asm volatile("cp.async.commit_group;" ::: "memory");
        } else {
            asm volatile("cp.async.commit_group;" ::: "memory");
        }

        const uint32_t* As = sAm + s * 2048;
        const uint32_t* Bs = sBm + s * 2048;
#pragma unroll
        for (int ksp = 0; ksp < 2; ksp++) {
            uint4 af[4];
            uint2 bf[4];
#pragma unroll
            for (int mi = 0; mi < 4; mi++)
                af[mi] = *(const uint4*)&As[(((wy * 4 + mi) * 2 + ksp) << 7) + (lane << 2)];
#pragma unroll
            for (int ni = 0; ni < 4; ni++)
                bf[ni] = *(const uint2*)&Bs[(((wx * 4 + ni) * 2 + ksp) << 6) + (lane << 1)];
#pragma unroll
            for (int mi = 0; mi < 4; mi++)
#pragma unroll
                for (int ni = 0; ni < 4; ni++)
                    MMA_F16(acc[mi][ni], af[mi].x, af[mi].y, af[mi].z, af[mi].w,
                            bf[ni].x, bf[ni].y);
        }
    }

#pragma unroll
    for (int mi = 0; mi < 4; mi++) {
        int r0 = m0 + wy * 64 + mi * 16 + gid;
#pragma unroll
        for (int ni = 0; ni < 4; ni++) {
            int feat = n0 + wx * 32 + ni * 8 + 2 * tig;
            float2 bb = *(const float2*)&bias[feat];
            if (MODE == 0) {
                int sec = feat >> 10, hm = feat & 1023;
                float* p = (sec == 0) ? g_q : ((sec == 1) ? g_k : g_v);
                float sc = (sec == 1) ? 0.125f : 1.0f;
                int h = hm >> 6, d = hm & 63;
                float2 v0 = make_float2(f2tff((acc[mi][ni][0] + bb.x) * sc),
                                        f2tff((acc[mi][ni][1] + bb.y) * sc));
                float2 v1 = make_float2(f2tff((acc[mi][ni][2] + bb.x) * sc),
                                        f2tff((acc[mi][ni][3] + bb.y) * sc));
                *(float2*)&p[((h * Nn + r0) << 6) + d] = v0;
                *(float2*)&p[((h * Nn + r0 + 8) << 6) + d] = v1;
            } else {
                float2 v0 = make_float2(acc[mi][ni][0] + bb.x, acc[mi][ni][1] + bb.y);
                float2 v1 = make_float2(acc[mi][ni][2] + bb.x, acc[mi][ni][3] + bb.y);
                *(float2*)&out[(size_t)r0 * Dd + feat] = v0;
                *(float2*)&out[(size_t)(r0 + 8) * Dd + feat] = v1;
            }
        }
    }
}

// ---------------- fused banded attention + pos logits, 64q/512t (tf32) ----
#define QT 64
#define BND 288
#define ERWS 224
#define BP 68
#define SSP2 244
#define SQ_F (QT * BP)
#define SE_F (ERWS * BP)
#define SB_F (BND * BP)
#define SS_F (QT * SSP2)
#define ATTN_SMEM_BYTES ((SQ_F + SE_F + SB_F + SS_F) * 4)   // 219136

// store a (C, C+1) pair of output values as one fp16x2 A-frag word
__device__ __forceinline__ void store_afrag2(int R, int C, float v0, float v1) {
    int mt = R >> 4, ks16 = C >> 4;
    int r = R & 15, c = C & 15;
    int lane = ((r & 7) << 2) + ((c & 7) >> 1);
    int reg = (r >> 3) + ((c >> 3) << 1);
    g_Ap[((((size_t)mt * 64 + ks16) << 5) + lane) * 4 + reg] = f2h2(v0, v1);
}

__global__ void __launch_bounds__(512) attn_kernel()
{
    extern __shared__ __align__(16) float sm[];
    float* sQ = sm;
    float* sE = sm + SQ_F;
    float* sB = sm + SQ_F + SE_F;
    float* sS = sm + SQ_F + SE_F + SB_F;
    const uint32_t sQu = smem_u32(sQ);
    const uint32_t sEu = smem_u32(sE);
    const uint32_t sBu = smem_u32(sB);

    const int h = blockIdx.y;
    const int i0 = blockIdx.x * QT;
    const int jlo = i0 - RAD;
    const int t = threadIdx.x;
    const int w = t >> 5, lane = t & 31;
    const int gid = lane >> 2, tig = lane & 3;
    const int mw = w & 3, nw = w >> 2;

    const float* Qg = g_q + ((size_t)(h * Nn + i0) << 6);
    for (int idx = t; idx < QT * 16; idx += 512) {
        int qi = idx >> 4, d4 = (idx & 15) << 2;
        cp16(sQu + (uint32_t)(qi * BP + d4) * 4, Qg + (qi << 6) + d4);
    }
    const float* Eg = g_Et + (size_t)h * ERWS * HD;
    for (int idx = t; idx < ERWS * 16; idx += 512) {
        int r = idx >> 4, d4 = (idx & 15) << 2;
        cp16(sEu + (uint32_t)(r * BP + d4) * 4, Eg + r * HD + d4);
    }
    asm volatile("cp.async.commit_group;" ::: "memory");

    for (int idx = t; idx < BND * 16; idx += 512) {
        int jj = idx >> 4, d4 = (idx & 15) << 2;
        int j = jlo + jj;
        if (j >= 0 && j < Nn)
            cp16(sBu + (uint32_t)(jj * BP + d4) * 4,
                 g_k + (((size_t)(h * Nn) + j) << 6) + d4);
        else
            *(float4*)&sB[jj * BP + d4] = make_float4(0.f, 0.f, 0.f, 0.f);
    }
    asm volatile("cp.async.commit_group;" ::: "memory");

    asm volatile("cp.async.wait_group 1;" ::: "memory");
    __syncthreads();

    float pacc[7][4];
#pragma unroll
    for (int f = 0; f < 7; f++)
#pragma unroll
        for (int j = 0; j < 4; j++) pacc[f][j] = 0.f;
#pragma unroll
    for (int ks = 0; ks < 8; ks++) {
        int kb = ks * 8 + tig;
        uint32_t a0 = __float_as_uint(sQ[(mw * 16 + gid) * BP + kb]);
        uint32_t a1 = __float_as_uint(sQ[(mw * 16 + gid + 8) * BP + kb]);
        uint32_t a2 = __float_as_uint(sQ[(mw * 16 + gid) * BP + kb + 4]);
        uint32_t a3 = __float_as_uint(sQ[(mw * 16 + gid + 8) * BP + kb + 4]);
#pragma unroll
        for (int f = 0; f < 7; f++) {
            int nb = (nw * 7 + f) * 8;
            uint32_t b0 = __float_as_uint(sE[(nb + gid) * BP + kb]);
            uint32_t b1 = __float_as_uint(sE[(nb + gid) * BP + kb + 4]);
            MMA_TF32(pacc[f], a0, a1, a2, a3, b0, b1);
        }
    }

    asm volatile("cp.async.wait_group 0;" ::: "memory");
    __syncthreads();

    {
        float acc[7][4];
#pragma unroll
        for (int f = 0; f < 7; f++)
#pragma unroll
            for (int j = 0; j < 4; j++) acc[f][j] = 0.f;
#pragma unroll
        for (int ks = 0; ks < 8; ks++) {
            int kb = ks * 8 + tig;
            uint32_t a0 = __float_as_uint(sQ[(mw * 16 + gid) * BP + kb]);
            uint32_t a1 = __float_as_uint(sQ[(mw * 16 + gid + 8) * BP + kb]);
            uint32_t a2 = __float_as_uint(sQ[(mw * 16 + gid) * BP + kb + 4]);
            uint32_t a3 = __float_as_uint(sQ[(mw * 16 + gid + 8) * BP + kb + 4]);
#pragma unroll
            for (int f = 0; f < 7; f++) {
                int nb = (2 * mw + nw * 7 + f) * 8;
                uint32_t b0 = __float_as_uint(sB[(nb + gid) * BP + kb]);
                uint32_t b1 = __float_as_uint(sB[(nb + gid) * BP + kb + 4]);
                MMA_TF32(acc[f], a0, a1, a2, a3, b0, b1);
            }
        }
        int r0 = mw * 16 + gid;
#pragma unroll
        for (int f = 0; f < 7; f++) {
            int col = (nw * 7 + f) * 8 + 2 * tig;
            *(float2*)&sS[r0 * SSP2 + col] = make_float2(acc[f][0], acc[f][1]);
            *(float2*)&sS[(r0 + 8) * SSP2 + col] = make_float2(acc[f][2], acc[f][3]);
        }
    }
    __syncthreads();

    for (int idx = t; idx < BND * 16; idx += 512) {
        int jj = idx >> 4, d4 = (idx & 15) << 2;
        int j = jlo + jj;
        if (j >= 0 && j < Nn)
            cp16(sBu + (uint32_t)(jj * BP + d4) * 4,
                 g_v + (((size_t)(h * Nn) + j) << 6) + d4);
        else
            *(float4*)&sB[jj * BP + d4] = make_float4(0.f, 0.f, 0.f, 0.f);
    }
    asm volatile("cp.async.commit_group;" ::: "memory");

    {
        int rl0 = gid, rl1 = gid + 8;
        int q0 = mw * 16 + gid, q1 = q0 + 8;
#pragma unroll
        for (int f = 0; f < 7; f++) {
            int r = (nw * 7 + f) * 8 + 2 * tig;
            float* p0 = &sS[q0 * SSP2 + rl0 + r];
            p0[0] += pacc[f][0];
            p0[1] += pacc[f][1];
            float* p1 = &sS[q1 * SSP2 + rl1 + r];
            p1[0] += pacc[f][2];
            p1[1] += pacc[f][3];
        }
    }
    __syncthreads();

    {
        float v[4][7];
#pragma unroll
        for (int p = 0; p < 4; p++) {
            int qi = w * 4 + p;
            int ql = qi & 15;
            int i = i0 + qi;
#pragma unroll
            for (int u = 0; u < 7; u++) {
                int r = lane + u * 32;
                float val = -1e30f;
                if (r < NEMB) {
                    int j = i - RAD + r;
                    if (j >= 0 && j < Nn)
                        val = sS[qi * SSP2 + ql + r];
                }
                v[p][u] = val;
            }
        }
        float mx[4];
#pragma unroll
        for (int p = 0; p < 4; p++) {
            mx[p] = v[p][0];
#pragma unroll
            for (int u = 1; u < 7; u++) mx[p] = fmaxf(mx[p], v[p][u]);
        }
#pragma unroll
        for (int off = 16; off; off >>= 1)
#pragma unroll
            for (int p = 0; p < 4; p++)
                mx[p] = fmaxf(mx[p], __shfl_xor_sync(0xffffffffu, mx[p], off));
        float s[4] = {0.f, 0.f, 0.f, 0.f};
#pragma unroll
        for (int p = 0; p < 4; p++)
#pragma unroll
            for (int u = 0; u < 7; u++) {
                v[p][u] = (v[p][u] > -1e29f) ? __expf(v[p][u] - mx[p]) : 0.f;
                s[p] += v[p][u];
            }
#pragma unroll
        for (int off = 16; off; off >>= 1)
#pragma unroll
            for (int p = 0; p < 4; p++)
                s[p] += __shfl_xor_sync(0xffffffffu, s[p], off);
        float inv[4];
#pragma unroll
        for (int p = 0; p < 4; p++) inv[p] = 1.f / s[p];

#pragma unroll
        for (int p = 0; p < 4; p++) {
            int qi = w * 4 + p;
#pragma unroll
            for (int u = 0; u < 7; u++)
                sS[qi * SSP2 + lane + u * 32] = 0.f;
        }
        __syncwarp();
#pragma unroll
        for (int p = 0; p < 4; p++) {
            int qi = w * 4 + p;
            int ql = qi & 15;
#pragma unroll
            for (int u = 0; u < 7; u++) {
                int r = lane + u * 32;
                if (r < NEMB && v[p][u] != 0.f)
                    sS[qi * SSP2 + ql + r] = f2tff(v[p][u] * inv[p]);
            }
        }
    }
    asm volatile("cp.async.wait_group 0;" ::: "memory");
    __syncthreads();

    {
        float acc[2][4];
#pragma unroll
        for (int ff = 0; ff < 2; ff++)
#pragma unroll
            for (int j = 0; j < 4; j++) acc[ff][j] = 0.f;

#pragma unroll
        for (int ks = 0; ks < 27; ks++) {
            int kb = ks * 8 + tig;
            uint32_t a0 = __float_as_uint(sS[(mw * 16 + gid) * SSP2 + kb]);
            uint32_t a1 = __float_as_uint(sS[(mw * 16 + gid + 8) * SSP2 + kb]);
            uint32_t a2 = __float_as_uint(sS[(mw * 16 + gid) * SSP2 + kb + 4]);
            uint32_t a3 = __float_as_uint(sS[(mw * 16 + gid + 8) * SSP2 + kb + 4]);
            int vrow = mw * 16 + kb;
#pragma unroll
            for (int ff = 0; ff < 2; ff++) {
                int nd = (nw * 2 + ff) * 8 + gid;
                uint32_t b0 = __float_as_uint(sB[vrow * BP + nd]);
                uint32_t b1 = __float_as_uint(sB[(vrow + 4) * BP + nd]);
                MMA_TF32(acc[ff], a0, a1, a2, a3, b0, b1);
            }
        }
        int R0 = i0 + mw * 16 + gid;
        int R1 = R0 + 8;
#pragma unroll
        for (int ff = 0; ff < 2; ff++) {
            int C = h * 64 + (nw * 2 + ff) * 8 + 2 * tig;
            store_afrag2(R0, C, acc[ff][0], acc[ff][1]);
            store_afrag2(R1, C, acc[ff][2], acc[ff][3]);
        }
    }
}

// ---------------- launcher ------------------------------------------------
extern "C" void kernel_launch(void* const* d_in, const int* in_sizes, int n_in,
                              void* d_out, int out_size)
{
    (void)in_sizes; (void)n_in; (void)out_size;
    const float* x      = (const float*)d_in[0];
    const float* qkv_w  = (const float*)d_in[1];
    const float* qkv_b  = (const float*)d_in[2];
    const float* proj_w = (const float*)d_in[3];
    const float* proj_b = (const float*)d_in[4];
    const float* rel    = (const float*)d_in[5];
    float* out = (float*)d_out;

    cudaFuncSetAttribute(mma_gemm<0>, cudaFuncAttributeMaxDynamicSharedMemorySize,
                         GEMM_SMEM_BYTES);
    cudaFuncSetAttribute(mma_gemm<1>, cudaFuncAttributeMaxDynamicSharedMemorySize,
                         GEMM_SMEM_BYTES);
    cudaFuncSetAttribute(attn_kernel, cudaFuncAttributeMaxDynamicSharedMemorySize,
                         ATTN_SMEM_BYTES);

    // 1) packs: x (fp16 A-frags), qkv_w (fp16 B-frags), rel_emb (tf32)
    packA<<<(Nn / 16) * (Dd / 16) * 32 / 256, 256>>>(x, Nn, Dd);
    packB<<<(3 * Dd / 8) * (Dd / 16) * 32 / 256, 256>>>(qkv_w, 3 * Dd, Dd);
    packE<<<Hh * 224 * HD / 256, 256>>>(rel);
    // 2) QKV GEMM (fp16 m16n8k16): scatter q / k(scaled) / v as tf32
    mma_gemm<0><<<dim3(3 * Dd / 128, Nn / 128), 256, GEMM_SMEM_BYTES>>>(qkv_b,
                                                                        nullptr, Dd);
    // 3) fused pos + banded attention (tf32) -> g_Ap (fp16 A-frags)
    attn_kernel<<<dim3(Nn / QT, Hh), 512, ATTN_SMEM_BYTES>>>();
    // 4) pack proj_w (fp16 B-frags)
    packB<<<(Dd / 8) * (Dd / 16) * 32 / 256, 256>>>(proj_w, Dd, Dd);
    // 5) output projection (fp16 m16n8k16) -> d_out
    mma_gemm<1><<<dim3(Dd / 128, Nn / 128), 256, GEMM_SMEM_BYTES>>>(proj_b, out, Dd);
}

// round 15
// speedup vs baseline: 1.6381x; 1.1443x over previous
#include <cuda_runtime.h>
#include <cuda_fp16.h>
#include <cstdint>

#define Nn 2048
#define Dd 1024
#define Hh 16
#define HD 64
#define NEMB 199
#define RAD 99

// ---------------- scratch (device globals; no allocation) ----------------
__device__ uint32_t g_qh[Hh * Nn * 32];        // fp16x2 q rows
__device__ uint32_t g_kh[Hh * Nn * 32];        // fp16x2 k rows (pre-scaled 1/8)
__device__ uint32_t g_vT[Hh * 64 * 1152];      // fp16 V transposed [h][d][pad128|n|pad]
__device__ uint32_t g_Eh[Hh * 224 * 32];       // fp16x2 rel_emb, zero-padded rows
__device__ uint32_t g_Ap[Nn * Dd / 2];         // packed fp16 A frags
__device__ uint32_t g_Bp[3 * Dd * Dd / 2];     // packed fp16 B frags

// ---------------- common helpers ------------------------------------------
__device__ __forceinline__ uint32_t f2h2(float a, float b) {
    __half2 h = __floats2half2_rn(a, b);
    return *(uint32_t*)&h;
}
__device__ __forceinline__ uint32_t smem_u32(const void* p) {
    uint32_t a;
    asm("{ .reg .u64 t; cvta.to.shared.u64 t, %1; cvt.u32.u64 %0, t; }"
        : "=r"(a) : "l"(p));
    return a;
}
__device__ __forceinline__ void cp16(uint32_t dst, const void* src) {
    asm volatile("cp.async.cg.shared.global [%0], [%1], 16;" :: "r"(dst), "l"(src) : "memory");
}

#define MMA_F16(d, a0, a1, a2, a3, b0, b1) \
    asm volatile( \
        "mma.sync.aligned.m16n8k16.row.col.f32.f16.f16.f32 " \
        "{%0,%1,%2,%3}, {%4,%5,%6,%7}, {%8,%9}, {%0,%1,%2,%3};" \
        : "+f"((d)[0]), "+f"((d)[1]), "+f"((d)[2]), "+f"((d)[3]) \
        : "r"(a0), "r"(a1), "r"(a2), "r"(a3), "r"(b0), "r"(b1))

// ---------------- pack kernels: fp32 -> fp16 fragment layouts --------------
__global__ void __launch_bounds__(256) packA(const float* __restrict__ src,
                                             int rows, int K)
{
    int idx = blockIdx.x * 256 + threadIdx.x;
    int KS16 = K >> 4;
    int total = (rows >> 4) * KS16 * 32;
    if (idx >= total) return;
    int lane = idx & 31;
    int ks = (idx >> 5) % KS16;
    int mt = (idx >> 5) / KS16;
    int gid = lane >> 2, tig = lane & 3;
    int r0 = mt * 16 + gid, c0 = ks * 16 + 2 * tig;
    const float* p0 = src + (size_t)r0 * K + c0;
    const float* p1 = src + (size_t)(r0 + 8) * K + c0;
    uint4 o;
    o.x = f2h2(p0[0], p0[1]);
    o.y = f2h2(p1[0], p1[1]);
    o.z = f2h2(p0[8], p0[9]);
    o.w = f2h2(p1[8], p1[9]);
    *(uint4*)&g_Ap[(size_t)idx * 4] = o;
}

__global__ void __launch_bounds__(256) packB(const float* __restrict__ src,
                                             int rowsB, int K)
{
    int idx = blockIdx.x * 256 + threadIdx.x;
    int KS16 = K >> 4;
    int total = (rowsB >> 3) * KS16 * 32;
    if (idx >= total) return;
    int lane = idx & 31;
    int ks = (idx >> 5) % KS16;
    int nt = (idx >> 5) / KS16;
    int gid = lane >> 2, tig = lane & 3;
    int n = nt * 8 + gid, c0 = ks * 16 + 2 * tig;
    const float* p = src + (size_t)n * K + c0;
    uint2 o;
    o.x = f2h2(p[0], p[1]);
    o.y = f2h2(p[8], p[9]);
    *(uint2*)&g_Bp[(size_t)idx * 2] = o;
}

// fp16 rel_emb words, zero-padded rows [NEMB, 224)
__global__ void __launch_bounds__(256) packE(const float* __restrict__ rel)
{
    int idx = blockIdx.x * 256 + threadIdx.x;
    if (idx >= Hh * 224 * 32) return;
    int wc = idx & 31;
    int r = (idx >> 5) % 224;
    int h = idx / (224 * 32);
    float v0 = 0.f, v1 = 0.f;
    if (r < NEMB) {
        const float* p = rel + ((size_t)h * NEMB + r) * HD + wc * 2;
        v0 = p[0]; v1 = p[1];
    }
    g_Eh[idx] = f2h2(v0, v1);
}

// ---------------- fp16 mma.sync GEMM, 128x128 tile, 3-stage cp.async ------
#define GEMM_SMEM_BYTES 49152

template <int MODE>
__global__ void __launch_bounds__(256, 2) mma_gemm(
    const float* __restrict__ bias, float* __restrict__ out, int K)
{
    extern __shared__ __align__(16) uint32_t smem[];
    uint32_t* sAm = smem;
    uint32_t* sBm = smem + 6144;
    const uint32_t sAu = smem_u32(sAm);
    const uint32_t sBu = smem_u32(sBm);

    const int t = threadIdx.x;
    const int KS16 = K >> 4;
    const int m0 = blockIdx.y * 128;
    const int n0 = blockIdx.x * 128;
    const int w = t >> 5, lane = t & 31;
    const int wy = w >> 2, wx = w & 3;
    const int gid = lane >> 2, tig = lane & 3;

    const uint32_t* Abase = g_Ap + (size_t)(blockIdx.y * 8) * KS16 * 128;
    const uint32_t* Bbase = g_Bp + (size_t)(blockIdx.x * 16) * KS16 * 64;

    float acc[4][4][4];
#pragma unroll
    for (int mi = 0; mi < 4; mi++)
#pragma unroll
        for (int ni = 0; ni < 4; ni++)
#pragma unroll
            for (int j = 0; j < 4; j++) acc[mi][ni][j] = 0.f;

    const int nc = K / 32;

    auto load_chunk = [&](int c, int s) {
        uint32_t ab = sAu + (uint32_t)s * 8192u;
        uint32_t bb = sBu + (uint32_t)s * 8192u;
#pragma unroll
        for (int q = 0; q < 2; q++) {
            int i4 = t + q * 256;
            int mt = i4 >> 6, rema = (i4 & 63) << 2;
            cp16(ab + (uint32_t)i4 * 16,
                 Abase + (size_t)mt * KS16 * 128 + c * 256 + rema);
            int nt = i4 >> 5, remb = (i4 & 31) << 2;
            cp16(bb + (uint32_t)i4 * 16,
                 Bbase + (size_t)nt * KS16 * 64 + c * 128 + remb);
        }
    };

    load_chunk(0, 0);
    asm volatile("cp.async.commit_group;" ::: "memory");
    load_chunk(1, 1);
    asm volatile("cp.async.commit_group;" ::: "memory");

    for (int c = 0; c < nc; ++c) {
        int s = c - (c / 3) * 3;
        asm volatile("cp.async.wait_group 1;" ::: "memory");
        __syncthreads();
        if (c + 2 < nc) {
            int s2 = (c + 2) - ((c + 2) / 3) * 3;
            load_chunk(c + 2, s2);
            asm volatile("cp.async.commit_group;" ::: "memory");
        } else {
            asm volatile("cp.async.commit_group;" ::: "memory");
        }

        const uint32_t* As = sAm + s * 2048;
        const uint32_t* Bs = sBm + s * 2048;
#pragma unroll
        for (int ksp = 0; ksp < 2; ksp++) {
            uint4 af[4];
            uint2 bf[4];
#pragma unroll
            for (int mi = 0; mi < 4; mi++)
                af[mi] = *(const uint4*)&As[(((wy * 4 + mi) * 2 + ksp) << 7) + (lane << 2)];
#pragma unroll
            for (int ni = 0; ni < 4; ni++)
                bf[ni] = *(const uint2*)&Bs[(((wx * 4 + ni) * 2 + ksp) << 6) + (lane << 1)];
#pragma unroll
            for (int mi = 0; mi < 4; mi++)
#pragma unroll
                for (int ni = 0; ni < 4; ni++)
                    MMA_F16(acc[mi][ni], af[mi].x, af[mi].y, af[mi].z, af[mi].w,
                            bf[ni].x, bf[ni].y);
        }
    }

#pragma unroll
    for (int mi = 0; mi < 4; mi++) {
        int r0 = m0 + wy * 64 + mi * 16 + gid;
#pragma unroll
        for (int ni = 0; ni < 4; ni++) {
            int feat = n0 + wx * 32 + ni * 8 + 2 * tig;
            float2 bb = *(const float2*)&bias[feat];
            if (MODE == 0) {
                int sec = feat >> 10, hm = feat & 1023;
                int h = hm >> 6, d = hm & 63;
                if (sec < 2) {
                    uint32_t* dst = (sec == 0) ? g_qh : g_kh;
                    float sc = (sec == 1) ? 0.125f : 1.0f;
                    dst[((size_t)(h * Nn + r0) << 5) + (d >> 1)] =
                        f2h2((acc[mi][ni][0] + bb.x) * sc, (acc[mi][ni][1] + bb.y) * sc);
                    dst[((size_t)(h * Nn + r0 + 8) << 5) + (d >> 1)] =
                        f2h2((acc[mi][ni][2] + bb.x) * sc, (acc[mi][ni][3] + bb.y) * sc);
                } else {
                    __half* vt = (__half*)g_vT;
                    size_t b0 = (size_t)(h * 64 + d) * 2304 + 128;
                    size_t b1 = (size_t)(h * 64 + d + 1) * 2304 + 128;
                    vt[b0 + r0]     = __float2half_rn(acc[mi][ni][0] + bb.x);
                    vt[b1 + r0]     = __float2half_rn(acc[mi][ni][1] + bb.y);
                    vt[b0 + r0 + 8] = __float2half_rn(acc[mi][ni][2] + bb.x);
                    vt[b1 + r0 + 8] = __float2half_rn(acc[mi][ni][3] + bb.y);
                }
            } else {
                float2 v0 = make_float2(acc[mi][ni][0] + bb.x, acc[mi][ni][1] + bb.y);
                float2 v1 = make_float2(acc[mi][ni][2] + bb.x, acc[mi][ni][3] + bb.y);
                *(float2*)&out[(size_t)r0 * Dd + feat] = v0;
                *(float2*)&out[(size_t)(r0 + 8) * Dd + feat] = v1;
            }
        }
    }
}

// ---------------- fused banded attention, all-fp16 operands ---------------
#define QT 64
#define BND 288
#define ERWS 224
#define KWP 36         // word pitch Q/E/K rows (32 data + 4)
#define PWP 116        // word pitch P rows (112 data + 4)
#define VWP 164        // word pitch Vt rows (144 data + 20)
#define SSP2 244       // fp32 S pitch
#define SQ_W (QT * KWP)                  // 2304
#define R2_W 8064                        // max(E 224*36, P 64*116)
#define R3_W 10496                       // max(K 288*36, Vt 64*164)
#define SS_F (QT * SSP2)                 // 15616
#define ATTN_SMEM_BYTES ((SQ_W + R2_W + R3_W + SS_F) * 4)   // 145920

__device__ __forceinline__ void store_afrag2(int R, int C, float v0, float v1) {
    int mt = R >> 4, ks16 = C >> 4;
    int r = R & 15, c = C & 15;
    int lane = ((r & 7) << 2) + ((c & 7) >> 1);
    int reg = (r >> 3) + ((c >> 3) << 1);
    g_Ap[((((size_t)mt * 64 + ks16) << 5) + lane) * 4 + reg] = f2h2(v0, v1);
}

__global__ void __launch_bounds__(512) attn_kernel()
{
    extern __shared__ __align__(16) uint32_t smw[];
    uint32_t* sQw = smw;                         // [64][KWP]
    uint32_t* sEw = smw + SQ_W;                  // E then P
    uint32_t* sBw = smw + SQ_W + R2_W;           // K band then Vt
    float* sS = (float*)(smw + SQ_W + R2_W + R3_W);
    const uint32_t sQu = smem_u32(sQw);
    const uint32_t sEu = smem_u32(sEw);
    const uint32_t sBu = smem_u32(sBw);

    const int h = blockIdx.y;
    const int i0 = blockIdx.x * QT;
    const int JLO = i0 - 104;                    // 8-half aligned band start
    const int t = threadIdx.x;
    const int w = t >> 5, lane = t & 31;
    const int gid = lane >> 2, tig = lane & 3;
    const int mw = w & 3, nw = w >> 2;

    // ---- Q fill (64 x 8 chunks = 512) + E fill (group A) ----
    {
        int qi = t >> 3, c8 = (t & 7) << 2;
        cp16(sQu + (uint32_t)(qi * KWP + c8) * 4,
             g_qh + (((size_t)(h * Nn + i0 + qi)) << 5) + c8);
    }
    for (int idx = t; idx < ERWS * 8; idx += 512) {
        int r = idx >> 3, c8 = (idx & 7) << 2;
        cp16(sEu + (uint32_t)(r * KWP + c8) * 4,
             g_Eh + (((size_t)(h * ERWS + r)) << 5) + c8);
    }
    asm volatile("cp.async.commit_group;" ::: "memory");

    // ---- K band fill (group B) ----
    for (int idx = t; idx < BND * 8; idx += 512) {
        int jj = idx >> 3, c8 = (idx & 7) << 2;
        int j = JLO + jj;
        if (j >= 0 && j < Nn)
            cp16(sBu + (uint32_t)(jj * KWP + c8) * 4,
                 g_kh + (((size_t)(h * Nn + j)) << 5) + c8);
        else {
            uint4 z = {0, 0, 0, 0};
            *(uint4*)&sBw[jj * KWP + c8] = z;
        }
    }
    asm volatile("cp.async.commit_group;" ::: "memory");

    asm volatile("cp.async.wait_group 1;" ::: "memory");
    __syncthreads();

    // ---- Spos = Q @ E^T (fp16, 4 k16-steps, 7 frags/warp) ----
    float pacc[7][4];
#pragma unroll
    for (int f = 0; f < 7; f++)
#pragma unroll
        for (int j = 0; j < 4; j++) pacc[f][j] = 0.f;
#pragma unroll
    for (int ks = 0; ks < 4; ks++) {
        int kb = ks * 8 + tig;
        uint32_t a0 = sQw[(mw * 16 + gid) * KWP + kb];
        uint32_t a1 = sQw[(mw * 16 + gid + 8) * KWP + kb];
        uint32_t a2 = sQw[(mw * 16 + gid) * KWP + kb + 4];
        uint32_t a3 = sQw[(mw * 16 + gid + 8) * KWP + kb + 4];
#pragma unroll
        for (int f = 0; f < 7; f++) {
            int nb = (nw * 7 + f) * 8 + gid;
            uint32_t b0 = sEw[nb * KWP + kb];
            uint32_t b1 = sEw[nb * KWP + kb + 4];
            MMA_F16(pacc[f], a0, a1, a2, a3, b0, b1);
        }
    }

    asm volatile("cp.async.wait_group 0;" ::: "memory");
    __syncthreads();

    // ---- Sqk band-restricted (fp16) -> fp32 band-relative S ----
    {
        float acc[7][4];
#pragma unroll
        for (int f = 0; f < 7; f++)
#pragma unroll
            for (int j = 0; j < 4; j++) acc[f][j] = 0.f;
#pragma unroll
        for (int ks = 0; ks < 4; ks++) {
            int kb = ks * 8 + tig;
            uint32_t a0 = sQw[(mw * 16 + gid) * KWP + kb];
            uint32_t a1 = sQw[(mw * 16 + gid + 8) * KWP + kb];
            uint32_t a2 = sQw[(mw * 16 + gid) * KWP + kb + 4];
            uint32_t a3 = sQw[(mw * 16 + gid + 8) * KWP + kb + 4];
#pragma unroll
            for (int f = 0; f < 7; f++) {
                int nb = (2 * mw + nw * 7 + f) * 8 + gid;
                uint32_t b0 = sBw[nb * KWP + kb];
                uint32_t b1 = sBw[nb * KWP + kb + 4];
                MMA_F16(acc[f], a0, a1, a2, a3, b0, b1);
            }
        }
        int r0 = mw * 16 + gid;
#pragma unroll
        for (int f = 0; f < 7; f++) {
            int col = (nw * 7 + f) * 8 + 2 * tig;   // local = band - 16mw
            *(float2*)&sS[r0 * SSP2 + col] = make_float2(acc[f][0], acc[f][1]);
            *(float2*)&sS[(r0 + 8) * SSP2 + col] = make_float2(acc[f][2], acc[f][3]);
        }
    }
    __syncthreads();

    // ---- issue Vt fill (overwrites K region): 64 rows x 36 cp16 ----
    for (int idx = t; idx < 64 * 36; idx += 512) {
        int d = idx / 36, wc = (idx % 36) << 2;
        cp16(sBu + (uint32_t)(d * VWP + wc) * 4,
             g_vT + (size_t)(h * 64 + d) * 1152 + 64 + (JLO >> 1) + wc);
    }
    asm volatile("cp.async.commit_group;" ::: "memory");

    // ---- merge pos into S: local col = ql + 5 + r ----
    {
        int rl0 = gid + 5, rl1 = gid + 13;
        int q0 = mw * 16 + gid, q1 = q0 + 8;
#pragma unroll
        for (int f = 0; f < 7; f++) {
            int r = (nw * 7 + f) * 8 + 2 * tig;
            float* p0 = &sS[q0 * SSP2 + rl0 + r];
            p0[0] += pacc[f][0];
            p0[1] += pacc[f][1];
            float* p1 = &sS[q1 * SSP2 + rl1 + r];
            p1[0] += pacc[f][2];
            p1[1] += pacc[f][3];
        }
    }
    __syncthreads();

    // ---- banded softmax (fp32), writes P as fp16 into sEw region ----
    {
        __half* sPh = (__half*)sEw;
        float v[4][7];
#pragma unroll
        for (int p = 0; p < 4; p++) {
            int qi = w * 4 + p;
            int ql = qi & 15;
            int i = i0 + qi;
#pragma unroll
            for (int u = 0; u < 7; u++) {
                int r = lane + u * 32;
                float val = -1e30f;
                if (r < NEMB) {
                    int j = i - RAD + r;
                    if (j >= 0 && j < Nn)
                        val = sS[qi * SSP2 + ql + 5 + r];
                }
                v[p][u] = val;
            }
        }
        float mx[4];
#pragma unroll
        for (int p = 0; p < 4; p++) {
            mx[p] = v[p][0];
#pragma unroll
            for (int u = 1; u < 7; u++) mx[p] = fmaxf(mx[p], v[p][u]);
        }
#pragma unroll
        for (int off = 16; off; off >>= 1)
#pragma unroll
            for (int p = 0; p < 4; p++)
                mx[p] = fmaxf(mx[p], __shfl_xor_sync(0xffffffffu, mx[p], off));
        float s[4] = {0.f, 0.f, 0.f, 0.f};
#pragma unroll
        for (int p = 0; p < 4; p++)
#pragma unroll
            for (int u = 0; u < 7; u++) {
                v[p][u] = (v[p][u] > -1e29f) ? __expf(v[p][u] - mx[p]) : 0.f;
                s[p] += v[p][u];
            }
#pragma unroll
        for (int off = 16; off; off >>= 1)
#pragma unroll
            for (int p = 0; p < 4; p++)
                s[p] += __shfl_xor_sync(0xffffffffu, s[p], off);
        float inv[4];
#pragma unroll
        for (int p = 0; p < 4; p++) inv[p] = 1.f / s[p];

        // zero P words [0,112) per row, then write band values
#pragma unroll
        for (int p = 0; p < 4; p++) {
            int qi = w * 4 + p;
#pragma unroll
            for (int u = 0; u < 4; u++) {
                int wd = lane + u * 32;
                if (wd < 112) sEw[qi * PWP + wd] = 0u;
            }
        }
        __syncwarp();
#pragma unroll
        for (int p = 0; p < 4; p++) {
            int qi = w * 4 + p;
            int ql = qi & 15;
#pragma unroll
            for (int u = 0; u < 7; u++) {
                int r = lane + u * 32;
                if (r < NEMB && v[p][u] != 0.f)
                    sPh[qi * (PWP * 2) + ql + 5 + r] =
                        __float2half_rn(v[p][u] * inv[p]);
            }
        }
    }
    asm volatile("cp.async.wait_group 0;" ::: "memory");
    __syncthreads();

    // ---- O = P @ Vt (fp16, 14 k16-steps) ----
    {
        float acc[2][4];
#pragma unroll
        for (int ff = 0; ff < 2; ff++)
#pragma unroll
            for (int j = 0; j < 4; j++) acc[ff][j] = 0.f;

#pragma unroll
        for (int ks = 0; ks < 14; ks++) {
            int kb = ks * 8 + tig;
            uint32_t a0 = sEw[(mw * 16 + gid) * PWP + kb];
            uint32_t a1 = sEw[(mw * 16 + gid + 8) * PWP + kb];
            uint32_t a2 = sEw[(mw * 16 + gid) * PWP + kb + 4];
            uint32_t a3 = sEw[(mw * 16 + gid + 8) * PWP + kb + 4];
#pragma unroll
            for (int ff = 0; ff < 2; ff++) {
                int nd = (nw * 2 + ff) * 8 + gid;
                uint32_t b0 = sBw[nd * VWP + mw * 8 + kb];
                uint32_t b1 = sBw[nd * VWP + mw * 8 + kb + 4];
                MMA_F16(acc[ff], a0, a1, a2, a3, b0, b1);
            }
        }
        int R0 = i0 + mw * 16 + gid;
        int R1 = R0 + 8;
#pragma unroll
        for (int ff = 0; ff < 2; ff++) {
            int C = h * 64 + (nw * 2 + ff) * 8 + 2 * tig;
            store_afrag2(R0, C, acc[ff][0], acc[ff][1]);
            store_afrag2(R1, C, acc[ff][2], acc[ff][3]);
        }
    }
}

// ---------------- launcher ------------------------------------------------
extern "C" void kernel_launch(void* const* d_in, const int* in_sizes, int n_in,
                              void* d_out, int out_size)
{
    (void)in_sizes; (void)n_in; (void)out_size;
    const float* x      = (const float*)d_in[0];
    const float* qkv_w  = (const float*)d_in[1];
    const float* qkv_b  = (const float*)d_in[2];
    const float* proj_w = (const float*)d_in[3];
    const float* proj_b = (const float*)d_in[4];
    const float* rel    = (const float*)d_in[5];
    float* out = (float*)d_out;

    cudaFuncSetAttribute(mma_gemm<0>, cudaFuncAttributeMaxDynamicSharedMemorySize,
                         GEMM_SMEM_BYTES);
    cudaFuncSetAttribute(mma_gemm<1>, cudaFuncAttributeMaxDynamicSharedMemorySize,
                         GEMM_SMEM_BYTES);
    cudaFuncSetAttribute(attn_kernel, cudaFuncAttributeMaxDynamicSharedMemorySize,
                         ATTN_SMEM_BYTES);

    // 1) packs: x (fp16 A-frags), qkv_w (fp16 B-frags), rel_emb (fp16 words)
    packA<<<(Nn / 16) * (Dd / 16) * 32 / 256, 256>>>(x, Nn, Dd);
    packB<<<(3 * Dd / 8) * (Dd / 16) * 32 / 256, 256>>>(qkv_w, 3 * Dd, Dd);
    packE<<<Hh * 224 * 32 / 256, 256>>>(rel);
    // 2) QKV GEMM (fp16): emit fp16 q/k rows + transposed fp16 V
    mma_gemm<0><<<dim3(3 * Dd / 128, Nn / 128), 256, GEMM_SMEM_BYTES>>>(qkv_b,
                                                                        nullptr, Dd);
    // 3) fused pos + banded attention (fp16) -> g_Ap (fp16 A-frags)
    attn_kernel<<<dim3(Nn / QT, Hh), 512, ATTN_SMEM_BYTES>>>();
    // 4) pack proj_w (fp16 B-frags)
    packB<<<(Dd / 8) * (Dd / 16) * 32 / 256, 256>>>(proj_w, Dd, Dd);
    // 5) output projection (fp16) -> d_out
    mma_gemm<1><<<dim3(Dd / 128, Nn / 128), 256, GEMM_SMEM_BYTES>>>(proj_b, out, Dd);
}

// round 16
// speedup vs baseline: 1.7682x; 1.0794x over previous
#include <cuda_runtime.h>
#include <cuda_fp16.h>
#include <cstdint>

#define Nn 2048
#define Dd 1024
#define Hh 16
#define HD 64
#define NEMB 199
#define RAD 99

// ---------------- scratch (device globals; no allocation) ----------------
__device__ uint32_t g_qh[Hh * Nn * 32];        // fp16x2 q rows
__device__ uint32_t g_kh[Hh * Nn * 32];        // fp16x2 k rows (pre-scaled 1/8)
__device__ uint32_t g_vT[Hh * 64 * 1152];      // fp16 V transposed [h][d][pad128|n|pad]
__device__ uint32_t g_Eh[Hh * 224 * 32];       // fp16x2 rel_emb, zero-padded rows
__device__ uint32_t g_Ap[Nn * Dd / 2];         // packed fp16 A frags
__device__ uint32_t g_Bp[3 * Dd * Dd / 2];     // packed fp16 B frags

// ---------------- common helpers ------------------------------------------
__device__ __forceinline__ uint32_t f2h2(float a, float b) {
    __half2 h = __floats2half2_rn(a, b);
    return *(uint32_t*)&h;
}
__device__ __forceinline__ uint32_t smem_u32(const void* p) {
    uint32_t a;
    asm("{ .reg .u64 t; cvta.to.shared.u64 t, %1; cvt.u32.u64 %0, t; }"
        : "=r"(a) : "l"(p));
    return a;
}
__device__ __forceinline__ void cp16(uint32_t dst, const void* src) {
    asm volatile("cp.async.cg.shared.global [%0], [%1], 16;" :: "r"(dst), "l"(src) : "memory");
}

#define MMA_F16(d, a0, a1, a2, a3, b0, b1) \
    asm volatile( \
        "mma.sync.aligned.m16n8k16.row.col.f32.f16.f16.f32 " \
        "{%0,%1,%2,%3}, {%4,%5,%6,%7}, {%8,%9}, {%0,%1,%2,%3};" \
        : "+f"((d)[0]), "+f"((d)[1]), "+f"((d)[2]), "+f"((d)[3]) \
        : "r"(a0), "r"(a1), "r"(a2), "r"(a3), "r"(b0), "r"(b1))

// ---------------- pack kernels: fp32 -> fp16 fragment layouts --------------
__global__ void __launch_bounds__(256) packA(const float* __restrict__ src,
                                             int rows, int K)
{
    int idx = blockIdx.x * 256 + threadIdx.x;
    int KS16 = K >> 4;
    int total = (rows >> 4) * KS16 * 32;
    if (idx >= total) return;
    int lane = idx & 31;
    int ks = (idx >> 5) % KS16;
    int mt = (idx >> 5) / KS16;
    int gid = lane >> 2, tig = lane & 3;
    int r0 = mt * 16 + gid, c0 = ks * 16 + 2 * tig;
    const float* p0 = src + (size_t)r0 * K + c0;
    const float* p1 = src + (size_t)(r0 + 8) * K + c0;
    uint4 o;
    o.x = f2h2(p0[0], p0[1]);
    o.y = f2h2(p1[0], p1[1]);
    o.z = f2h2(p0[8], p0[9]);
    o.w = f2h2(p1[8], p1[9]);
    *(uint4*)&g_Ap[(size_t)idx * 4] = o;
}

__global__ void __launch_bounds__(256) packB(const float* __restrict__ src,
                                             int rowsB, int K)
{
    int idx = blockIdx.x * 256 + threadIdx.x;
    int KS16 = K >> 4;
    int total = (rowsB >> 3) * KS16 * 32;
    if (idx >= total) return;
    int lane = idx & 31;
    int ks = (idx >> 5) % KS16;
    int nt = (idx >> 5) / KS16;
    int gid = lane >> 2, tig = lane & 3;
    int n = nt * 8 + gid, c0 = ks * 16 + 2 * tig;
    const float* p = src + (size_t)n * K + c0;
    uint2 o;
    o.x = f2h2(p[0], p[1]);
    o.y = f2h2(p[8], p[9]);
    *(uint2*)&g_Bp[(size_t)idx * 2] = o;
}

// fp16 rel_emb words, zero-padded rows [NEMB, 224)
__global__ void __launch_bounds__(256) packE(const float* __restrict__ rel)
{
    int idx = blockIdx.x * 256 + threadIdx.x;
    if (idx >= Hh * 224 * 32) return;
    int wc = idx & 31;
    int r = (idx >> 5) % 224;
    int h = idx / (224 * 32);
    float v0 = 0.f, v1 = 0.f;
    if (r < NEMB) {
        const float* p = rel + ((size_t)h * NEMB + r) * HD + wc * 2;
        v0 = p[0]; v1 = p[1];
    }
    g_Eh[idx] = f2h2(v0, v1);
}

// ---------------- fp16 mma.sync GEMM, 128x128 tile, BK=64, 3 stages -------
#define GEMM_SMEM_BYTES 98304    // 3 stages x (16KB A + 16KB B)

template <int MODE>
__global__ void __launch_bounds__(256, 2) mma_gemm(
    const float* __restrict__ bias, float* __restrict__ out, int K)
{
    extern __shared__ __align__(16) uint32_t smem[];
    uint32_t* sAm = smem;                 // [3][4096]
    uint32_t* sBm = smem + 12288;         // [3][4096]
    const uint32_t sAu = smem_u32(sAm);
    const uint32_t sBu = smem_u32(sBm);

    const int t = threadIdx.x;
    const int KS16 = K >> 4;
    const int m0 = blockIdx.y * 128;
    const int n0 = blockIdx.x * 128;
    const int w = t >> 5, lane = t & 31;
    const int wy = w >> 2, wx = w & 3;
    const int gid = lane >> 2, tig = lane & 3;

    const uint32_t* Abase = g_Ap + (size_t)(blockIdx.y * 8) * KS16 * 128;
    const uint32_t* Bbase = g_Bp + (size_t)(blockIdx.x * 16) * KS16 * 64;

    float acc[4][4][4];
#pragma unroll
    for (int mi = 0; mi < 4; mi++)
#pragma unroll
        for (int ni = 0; ni < 4; ni++)
#pragma unroll
            for (int j = 0; j < 4; j++) acc[mi][ni][j] = 0.f;

    const int nc = K / 64;    // chunk = 4 k16-slices

    auto load_chunk = [&](int c, int s) {
        uint32_t ab = sAu + (uint32_t)s * 16384u;
        uint32_t bb = sBu + (uint32_t)s * 16384u;
#pragma unroll
        for (int q = 0; q < 4; q++) {
            int i4 = t + q * 256;                   // 0..1023
            int mt = i4 >> 7, rema = (i4 & 127) << 2;
            cp16(ab + (uint32_t)i4 * 16,
                 Abase + (size_t)mt * KS16 * 128 + c * 512 + rema);
            int nt = i4 >> 6, remb = (i4 & 63) << 2;
            cp16(bb + (uint32_t)i4 * 16,
                 Bbase + (size_t)nt * KS16 * 64 + c * 256 + remb);
        }
    };

    load_chunk(0, 0);
    asm volatile("cp.async.commit_group;" ::: "memory");
    load_chunk(1, 1);
    asm volatile("cp.async.commit_group;" ::: "memory");

    for (int c = 0; c < nc; ++c) {
        int s = c - (c / 3) * 3;
        asm volatile("cp.async.wait_group 1;" ::: "memory");
        __syncthreads();
        if (c + 2 < nc) {
            int s2 = (c + 2) - ((c + 2) / 3) * 3;
            load_chunk(c + 2, s2);
            asm volatile("cp.async.commit_group;" ::: "memory");
        } else {
            asm volatile("cp.async.commit_group;" ::: "memory");
        }

        const uint32_t* As = sAm + s * 4096;
        const uint32_t* Bs = sBm + s * 4096;
#pragma unroll
        for (int ksp = 0; ksp < 4; ksp++) {
            uint4 af[4];
            uint2 bf[4];
#pragma unroll
            for (int mi = 0; mi < 4; mi++)
                af[mi] = *(const uint4*)&As[(((wy * 4 + mi) * 4 + ksp) << 7) + (lane << 2)];
#pragma unroll
            for (int ni = 0; ni < 4; ni++)
                bf[ni] = *(const uint2*)&Bs[(((wx * 4 + ni) * 4 + ksp) << 6) + (lane << 1)];
#pragma unroll
            for (int mi = 0; mi < 4; mi++)
#pragma unroll
                for (int ni = 0; ni < 4; ni++)
                    MMA_F16(acc[mi][ni], af[mi].x, af[mi].y, af[mi].z, af[mi].w,
                            bf[ni].x, bf[ni].y);
        }
    }

#pragma unroll
    for (int mi = 0; mi < 4; mi++) {
        int r0 = m0 + wy * 64 + mi * 16 + gid;
#pragma unroll
        for (int ni = 0; ni < 4; ni++) {
            int feat = n0 + wx * 32 + ni * 8 + 2 * tig;
            float2 bb = *(const float2*)&bias[feat];
            if (MODE == 0) {
                int sec = feat >> 10, hm = feat & 1023;
                int h = hm >> 6, d = hm & 63;
                if (sec < 2) {
                    uint32_t* dst = (sec == 0) ? g_qh : g_kh;
                    float sc = (sec == 1) ? 0.125f : 1.0f;
                    dst[((size_t)(h * Nn + r0) << 5) + (d >> 1)] =
                        f2h2((acc[mi][ni][0] + bb.x) * sc, (acc[mi][ni][1] + bb.y) * sc);
                    dst[((size_t)(h * Nn + r0 + 8) << 5) + (d >> 1)] =
                        f2h2((acc[mi][ni][2] + bb.x) * sc, (acc[mi][ni][3] + bb.y) * sc);
                } else {
                    __half* vt = (__half*)g_vT;
                    size_t b0 = (size_t)(h * 64 + d) * 2304 + 128;
                    size_t b1 = (size_t)(h * 64 + d + 1) * 2304 + 128;
                    vt[b0 + r0]     = __float2half_rn(acc[mi][ni][0] + bb.x);
                    vt[b1 + r0]     = __float2half_rn(acc[mi][ni][1] + bb.y);
                    vt[b0 + r0 + 8] = __float2half_rn(acc[mi][ni][2] + bb.x);
                    vt[b1 + r0 + 8] = __float2half_rn(acc[mi][ni][3] + bb.y);
                }
            } else {
                float2 v0 = make_float2(acc[mi][ni][0] + bb.x, acc[mi][ni][1] + bb.y);
                float2 v1 = make_float2(acc[mi][ni][2] + bb.x, acc[mi][ni][3] + bb.y);
                *(float2*)&out[(size_t)r0 * Dd + feat] = v0;
                *(float2*)&out[(size_t)(r0 + 8) * Dd + feat] = v1;
            }
        }
    }
}

// ---------------- fused banded attention, all-fp16 operands ---------------
#define QT 64
#define BND 288
#define ERWS 224
#define KWP 36
#define PWP 116
#define VWP 164
#define SSP2 244
#define SQ_W (QT * KWP)
#define R2_W 8064
#define R3_W 10496
#define SS_F (QT * SSP2)
#define ATTN_SMEM_BYTES ((SQ_W + R2_W + R3_W + SS_F) * 4)   // 145920

__device__ __forceinline__ void store_afrag2(int R, int C, float v0, float v1) {
    int mt = R >> 4, ks16 = C >> 4;
    int r = R & 15, c = C & 15;
    int lane = ((r & 7) << 2) + ((c & 7) >> 1);
    int reg = (r >> 3) + ((c >> 3) << 1);
    g_Ap[((((size_t)mt * 64 + ks16) << 5) + lane) * 4 + reg] = f2h2(v0, v1);
}

__global__ void __launch_bounds__(512) attn_kernel()
{
    extern __shared__ __align__(16) uint32_t smw[];
    uint32_t* sQw = smw;
    uint32_t* sEw = smw + SQ_W;
    uint32_t* sBw = smw + SQ_W + R2_W;
    float* sS = (float*)(smw + SQ_W + R2_W + R3_W);
    const uint32_t sQu = smem_u32(sQw);
    const uint32_t sEu = smem_u32(sEw);
    const uint32_t sBu = smem_u32(sBw);

    const int h = blockIdx.y;
    const int i0 = blockIdx.x * QT;
    const int JLO = i0 - 104;
    const int t = threadIdx.x;
    const int w = t >> 5, lane = t & 31;
    const int gid = lane >> 2, tig = lane & 3;
    const int mw = w & 3, nw = w >> 2;

    {
        int qi = t >> 3, c8 = (t & 7) << 2;
        cp16(sQu + (uint32_t)(qi * KWP + c8) * 4,
             g_qh + (((size_t)(h * Nn + i0 + qi)) << 5) + c8);
    }
    for (int idx = t; idx < ERWS * 8; idx += 512) {
        int r = idx >> 3, c8 = (idx & 7) << 2;
        cp16(sEu + (uint32_t)(r * KWP + c8) * 4,
             g_Eh + (((size_t)(h * ERWS + r)) << 5) + c8);
    }
    asm volatile("cp.async.commit_group;" ::: "memory");

    for (int idx = t; idx < BND * 8; idx += 512) {
        int jj = idx >> 3, c8 = (idx & 7) << 2;
        int j = JLO + jj;
        if (j >= 0 && j < Nn)
            cp16(sBu + (uint32_t)(jj * KWP + c8) * 4,
                 g_kh + (((size_t)(h * Nn + j)) << 5) + c8);
        else {
            uint4 z = {0, 0, 0, 0};
            *(uint4*)&sBw[jj * KWP + c8] = z;
        }
    }
    asm volatile("cp.async.commit_group;" ::: "memory");

    asm volatile("cp.async.wait_group 1;" ::: "memory");
    __syncthreads();

    float pacc[7][4];
#pragma unroll
    for (int f = 0; f < 7; f++)
#pragma unroll
        for (int j = 0; j < 4; j++) pacc[f][j] = 0.f;
#pragma unroll
    for (int ks = 0; ks < 4; ks++) {
        int kb = ks * 8 + tig;
        uint32_t a0 = sQw[(mw * 16 + gid) * KWP + kb];
        uint32_t a1 = sQw[(mw * 16 + gid + 8) * KWP + kb];
        uint32_t a2 = sQw[(mw * 16 + gid) * KWP + kb + 4];
        uint32_t a3 = sQw[(mw * 16 + gid + 8) * KWP + kb + 4];
#pragma unroll
        for (int f = 0; f < 7; f++) {
            int nb = (nw * 7 + f) * 8 + gid;
            uint32_t b0 = sEw[nb * KWP + kb];
            uint32_t b1 = sEw[nb * KWP + kb + 4];
            MMA_F16(pacc[f], a0, a1, a2, a3, b0, b1);
        }
    }

    asm volatile("cp.async.wait_group 0;" ::: "memory");
    __syncthreads();

    {
        float acc[7][4];
#pragma unroll
        for (int f = 0; f < 7; f++)
#pragma unroll
            for (int j = 0; j < 4; j++) acc[f][j] = 0.f;
#pragma unroll
        for (int ks = 0; ks < 4; ks++) {
            int kb = ks * 8 + tig;
            uint32_t a0 = sQw[(mw * 16 + gid) * KWP + kb];
            uint32_t a1 = sQw[(mw * 16 + gid + 8) * KWP + kb];
            uint32_t a2 = sQw[(mw * 16 + gid) * KWP + kb + 4];
            uint32_t a3 = sQw[(mw * 16 + gid + 8) * KWP + kb + 4];
#pragma unroll
            for (int f = 0; f < 7; f++) {
                int nb = (2 * mw + nw * 7 + f) * 8 + gid;
                uint32_t b0 = sBw[nb * KWP + kb];
                uint32_t b1 = sBw[nb * KWP + kb + 4];
                MMA_F16(acc[f], a0, a1, a2, a3, b0, b1);
            }
        }
        int r0 = mw * 16 + gid;
#pragma unroll
        for (int f = 0; f < 7; f++) {
            int col = (nw * 7 + f) * 8 + 2 * tig;
            *(float2*)&sS[r0 * SSP2 + col] = make_float2(acc[f][0], acc[f][1]);
            *(float2*)&sS[(r0 + 8) * SSP2 + col] = make_float2(acc[f][2], acc[f][3]);
        }
    }
    __syncthreads();

    for (int idx = t; idx < 64 * 36; idx += 512) {
        int d = idx / 36, wc = (idx % 36) << 2;
        cp16(sBu + (uint32_t)(d * VWP + wc) * 4,
             g_vT + (size_t)(h * 64 + d) * 1152 + 64 + (JLO >> 1) + wc);
    }
    asm volatile("cp.async.commit_group;" ::: "memory");

    {
        int rl0 = gid + 5, rl1 = gid + 13;
        int q0 = mw * 16 + gid, q1 = q0 + 8;
#pragma unroll
        for (int f = 0; f < 7; f++) {
            int r = (nw * 7 + f) * 8 + 2 * tig;
            float* p0 = &sS[q0 * SSP2 + rl0 + r];
            p0[0] += pacc[f][0];
            p0[1] += pacc[f][1];
            float* p1 = &sS[q1 * SSP2 + rl1 + r];
            p1[0] += pacc[f][2];
            p1[1] += pacc[f][3];
        }
    }
    __syncthreads();

    {
        __half* sPh = (__half*)sEw;
        float v[4][7];
#pragma unroll
        for (int p = 0; p < 4; p++) {
            int qi = w * 4 + p;
            int ql = qi & 15;
            int i = i0 + qi;
#pragma unroll
            for (int u = 0; u < 7; u++) {
                int r = lane + u * 32;
                float val = -1e30f;
                if (r < NEMB) {
                    int j = i - RAD + r;
                    if (j >= 0 && j < Nn)
                        val = sS[qi * SSP2 + ql + 5 + r];
                }
                v[p][u] = val;
            }
        }
        float mx[4];
#pragma unroll
        for (int p = 0; p < 4; p++) {
            mx[p] = v[p][0];
#pragma unroll
            for (int u = 1; u < 7; u++) mx[p] = fmaxf(mx[p], v[p][u]);
        }
#pragma unroll
        for (int off = 16; off; off >>= 1)
#pragma unroll
            for (int p = 0; p < 4; p++)
                mx[p] = fmaxf(mx[p], __shfl_xor_sync(0xffffffffu, mx[p], off));
        float s[4] = {0.f, 0.f, 0.f, 0.f};
#pragma unroll
        for (int p = 0; p < 4; p++)
#pragma unroll
            for (int u = 0; u < 7; u++) {
                v[p][u] = (v[p][u] > -1e29f) ? __expf(v[p][u] - mx[p]) : 0.f;
                s[p] += v[p][u];
            }
#pragma unroll
        for (int off = 16; off; off >>= 1)
#pragma unroll
            for (int p = 0; p < 4; p++)
                s[p] += __shfl_xor_sync(0xffffffffu, s[p], off);
        float inv[4];
#pragma unroll
        for (int p = 0; p < 4; p++) inv[p] = 1.f / s[p];

#pragma unroll
        for (int p = 0; p < 4; p++) {
            int qi = w * 4 + p;
#pragma unroll
            for (int u = 0; u < 4; u++) {
                int wd = lane + u * 32;
                if (wd < 112) sEw[qi * PWP + wd] = 0u;
            }
        }
        __syncwarp();
#pragma unroll
        for (int p = 0; p < 4; p++) {
            int qi = w * 4 + p;
            int ql = qi & 15;
#pragma unroll
            for (int u = 0; u < 7; u++) {
                int r = lane + u * 32;
                if (r < NEMB && v[p][u] != 0.f)
                    sPh[qi * (PWP * 2) + ql + 5 + r] =
                        __float2half_rn(v[p][u] * inv[p]);
            }
        }
    }
    asm volatile("cp.async.wait_group 0;" ::: "memory");
    __syncthreads();

    {
        float acc[2][4];
#pragma unroll
        for (int ff = 0; ff < 2; ff++)
#pragma unroll
            for (int j = 0; j < 4; j++) acc[ff][j] = 0.f;

#pragma unroll
        for (int ks = 0; ks < 14; ks++) {
            int kb = ks * 8 + tig;
            uint32_t a0 = sEw[(mw * 16 + gid) * PWP + kb];
            uint32_t a1 = sEw[(mw * 16 + gid + 8) * PWP + kb];
            uint32_t a2 = sEw[(mw * 16 + gid) * PWP + kb + 4];
            uint32_t a3 = sEw[(mw * 16 + gid + 8) * PWP + kb + 4];
#pragma unroll
            for (int ff = 0; ff < 2; ff++) {
                int nd = (nw * 2 + ff) * 8 + gid;
                uint32_t b0 = sBw[nd * VWP + mw * 8 + kb];
                uint32_t b1 = sBw[nd * VWP + mw * 8 + kb + 4];
                MMA_F16(acc[ff], a0, a1, a2, a3, b0, b1);
            }
        }
        int R0 = i0 + mw * 16 + gid;
        int R1 = R0 + 8;
#pragma unroll
        for (int ff = 0; ff < 2; ff++) {
            int C = h * 64 + (nw * 2 + ff) * 8 + 2 * tig;
            store_afrag2(R0, C, acc[ff][0], acc[ff][1]);
            store_afrag2(R1, C, acc[ff][2], acc[ff][3]);
        }
    }
}

// ---------------- launcher ------------------------------------------------
extern "C" void kernel_launch(void* const* d_in, const int* in_sizes, int n_in,
                              void* d_out, int out_size)
{
    (void)in_sizes; (void)n_in; (void)out_size;
    const float* x      = (const float*)d_in[0];
    const float* qkv_w  = (const float*)d_in[1];
    const float* qkv_b  = (const float*)d_in[2];
    const float* proj_w = (const float*)d_in[3];
    const float* proj_b = (const float*)d_in[4];
    const float* rel    = (const float*)d_in[5];
    float* out = (float*)d_out;

    cudaFuncSetAttribute(mma_gemm<0>, cudaFuncAttributeMaxDynamicSharedMemorySize,
                         GEMM_SMEM_BYTES);
    cudaFuncSetAttribute(mma_gemm<1>, cudaFuncAttributeMaxDynamicSharedMemorySize,
                         GEMM_SMEM_BYTES);
    cudaFuncSetAttribute(attn_kernel, cudaFuncAttributeMaxDynamicSharedMemorySize,
                         ATTN_SMEM_BYTES);

    // 1) packs: x (fp16 A-frags), qkv_w (fp16 B-frags), rel_emb (fp16 words)
    packA<<<(Nn / 16) * (Dd / 16) * 32 / 256, 256>>>(x, Nn, Dd);
    packB<<<(3 * Dd / 8) * (Dd / 16) * 32 / 256, 256>>>(qkv_w, 3 * Dd, Dd);
    packE<<<Hh * 224 * 32 / 256, 256>>>(rel);
    // 2) QKV GEMM (fp16, BK=64): emit fp16 q/k rows + transposed fp16 V
    mma_gemm<0><<<dim3(3 * Dd / 128, Nn / 128), 256, GEMM_SMEM_BYTES>>>(qkv_b,
                                                                        nullptr, Dd);
    // 3) fused pos + banded attention (fp16) -> g_Ap (fp16 A-frags)
    attn_kernel<<<dim3(Nn / QT, Hh), 512, ATTN_SMEM_BYTES>>>();
    // 4) pack proj_w (fp16 B-frags)
    packB<<<(Dd / 8) * (Dd / 16) * 32 / 256, 256>>>(proj_w, Dd, Dd);
    // 5) output projection (fp16, BK=64) -> d_out
    mma_gemm<1><<<dim3(Dd / 128, Nn / 128), 256, GEMM_SMEM_BYTES>>>(proj_b, out, Dd);
}

// round 17
// speedup vs baseline: 1.9260x; 1.0892x over previous
#include <cuda_runtime.h>
#include <cuda_fp16.h>
#include <cstdint>

#define Nn 2048
#define Dd 1024
#define Hh 16
#define HD 64
#define NEMB 199
#define RAD 99

// ---------------- scratch (device globals; no allocation) ----------------
__device__ uint32_t g_qh[Hh * Nn * 32];        // fp16x2 q rows
__device__ uint32_t g_kh[Hh * Nn * 32];        // fp16x2 k rows (pre-scaled 1/8)
__device__ uint32_t g_vT[Hh * 64 * 1152];      // fp16 V transposed [h][d][pad128|n|pad]
__device__ uint32_t g_Eh[Hh * 224 * 32];       // fp16x2 rel_emb, zero-padded rows
__device__ uint32_t g_Ap[Nn * Dd / 2];         // packed fp16 A frags
__device__ uint32_t g_Bp[3 * Dd * Dd / 2];     // packed fp16 B frags (qkv_w)
__device__ uint32_t g_Bp2[Dd * Dd / 2];        // packed fp16 B frags (proj_w)

// ---------------- common helpers ------------------------------------------
__device__ __forceinline__ uint32_t f2h2(float a, float b) {
    __half2 h = __floats2half2_rn(a, b);
    return *(uint32_t*)&h;
}
__device__ __forceinline__ uint32_t smem_u32(const void* p) {
    uint32_t a;
    asm("{ .reg .u64 t; cvta.to.shared.u64 t, %1; cvt.u32.u64 %0, t; }"
        : "=r"(a) : "l"(p));
    return a;
}
__device__ __forceinline__ void cp16(uint32_t dst, const void* src) {
    asm volatile("cp.async.cg.shared.global [%0], [%1], 16;" :: "r"(dst), "l"(src) : "memory");
}

#define MMA_F16(d, a0, a1, a2, a3, b0, b1) \
    asm volatile( \
        "mma.sync.aligned.m16n8k16.row.col.f32.f16.f16.f32 " \
        "{%0,%1,%2,%3}, {%4,%5,%6,%7}, {%8,%9}, {%0,%1,%2,%3};" \
        : "+f"((d)[0]), "+f"((d)[1]), "+f"((d)[2]), "+f"((d)[3]) \
        : "r"(a0), "r"(a1), "r"(a2), "r"(a3), "r"(b0), "r"(b1))

// ---------------- merged pack kernel ---------------------------------------
// blocks [0,1024): A-frags of x      [1024,4096): B-frags of qkv_w
// blocks [4096,4544): fp16 rel_emb   [4544,5568): B-frags of proj_w -> g_Bp2
__global__ void __launch_bounds__(256) pack_all(
    const float* __restrict__ x, const float* __restrict__ qkv_w,
    const float* __restrict__ proj_w, const float* __restrict__ rel)
{
    int b = blockIdx.x;
    int tid = threadIdx.x;
    if (b < 1024) {                       // packA(x): rows 2048, K 1024
        int idx = b * 256 + tid;
        int lane = idx & 31;
        int ks = (idx >> 5) & 63;         // KS16 = 64
        int mt = (idx >> 5) >> 6;
        int gid = lane >> 2, tig = lane & 3;
        int r0 = mt * 16 + gid, c0 = ks * 16 + 2 * tig;
        const float* p0 = x + (size_t)r0 * Dd + c0;
        const float* p1 = x + (size_t)(r0 + 8) * Dd + c0;
        uint4 o;
        o.x = f2h2(p0[0], p0[1]);
        o.y = f2h2(p1[0], p1[1]);
        o.z = f2h2(p0[8], p0[9]);
        o.w = f2h2(p1[8], p1[9]);
        *(uint4*)&g_Ap[(size_t)idx * 4] = o;
    } else if (b < 4096) {                // packB(qkv_w): rowsB 3072, K 1024
        int idx = (b - 1024) * 256 + tid;
        int lane = idx & 31;
        int ks = (idx >> 5) & 63;
        int nt = (idx >> 5) >> 6;
        int gid = lane >> 2, tig = lane & 3;
        int n = nt * 8 + gid, c0 = ks * 16 + 2 * tig;
        const float* p = qkv_w + (size_t)n * Dd + c0;
        uint2 o;
        o.x = f2h2(p[0], p[1]);
        o.y = f2h2(p[8], p[9]);
        *(uint2*)&g_Bp[(size_t)idx * 2] = o;
    } else if (b < 4544) {                // packE
        int idx = (b - 4096) * 256 + tid;
        int wc = idx & 31;
        int r = (idx >> 5) % 224;
        int h = idx / (224 * 32);
        float v0 = 0.f, v1 = 0.f;
        if (r < NEMB) {
            const float* p = rel + ((size_t)h * NEMB + r) * HD + wc * 2;
            v0 = p[0]; v1 = p[1];
        }
        g_Eh[idx] = f2h2(v0, v1);
    } else {                              // packB(proj_w): rowsB 1024 -> g_Bp2
        int idx = (b - 4544) * 256 + tid;
        int lane = idx & 31;
        int ks = (idx >> 5) & 63;
        int nt = (idx >> 5) >> 6;
        int gid = lane >> 2, tig = lane & 3;
        int n = nt * 8 + gid, c0 = ks * 16 + 2 * tig;
        const float* p = proj_w + (size_t)n * Dd + c0;
        uint2 o;
        o.x = f2h2(p[0], p[1]);
        o.y = f2h2(p[8], p[9]);
        *(uint2*)&g_Bp2[(size_t)idx * 2] = o;
    }
}

// ---------------- fp16 mma.sync GEMM, 128x128 tile, BK=64, 3 stages -------
#define GEMM_SMEM_BYTES 98304

template <int MODE>
__global__ void __launch_bounds__(256, 2) mma_gemm(
    const float* __restrict__ bias, float* __restrict__ out, int K)
{
    extern __shared__ __align__(16) uint32_t smem[];
    uint32_t* sAm = smem;
    uint32_t* sBm = smem + 12288;
    const uint32_t sAu = smem_u32(sAm);
    const uint32_t sBu = smem_u32(sBm);

    const int t = threadIdx.x;
    const int KS16 = K >> 4;
    const int m0 = blockIdx.y * 128;
    const int n0 = blockIdx.x * 128;
    const int w = t >> 5, lane = t & 31;
    const int wy = w >> 2, wx = w & 3;
    const int gid = lane >> 2, tig = lane & 3;

    const uint32_t* Bsrc = (MODE == 0) ? g_Bp : g_Bp2;
    const uint32_t* Abase = g_Ap + (size_t)(blockIdx.y * 8) * KS16 * 128;
    const uint32_t* Bbase = Bsrc + (size_t)(blockIdx.x * 16) * KS16 * 64;

    float acc[4][4][4];
#pragma unroll
    for (int mi = 0; mi < 4; mi++)
#pragma unroll
        for (int ni = 0; ni < 4; ni++)
#pragma unroll
            for (int j = 0; j < 4; j++) acc[mi][ni][j] = 0.f;

    const int nc = K / 64;

    auto load_chunk = [&](int c, int s) {
        uint32_t ab = sAu + (uint32_t)s * 16384u;
        uint32_t bb = sBu + (uint32_t)s * 16384u;
#pragma unroll
        for (int q = 0; q < 4; q++) {
            int i4 = t + q * 256;
            int mt = i4 >> 7, rema = (i4 & 127) << 2;
            cp16(ab + (uint32_t)i4 * 16,
                 Abase + (size_t)mt * KS16 * 128 + c * 512 + rema);
            int nt = i4 >> 6, remb = (i4 & 63) << 2;
            cp16(bb + (uint32_t)i4 * 16,
                 Bbase + (size_t)nt * KS16 * 64 + c * 256 + remb);
        }
    };

    load_chunk(0, 0);
    asm volatile("cp.async.commit_group;" ::: "memory");
    load_chunk(1, 1);
    asm volatile("cp.async.commit_group;" ::: "memory");

    for (int c = 0; c < nc; ++c) {
        int s = c - (c / 3) * 3;
        asm volatile("cp.async.wait_group 1;" ::: "memory");
        __syncthreads();
        if (c + 2 < nc) {
            int s2 = (c + 2) - ((c + 2) / 3) * 3;
            load_chunk(c + 2, s2);
            asm volatile("cp.async.commit_group;" ::: "memory");
        } else {
            asm volatile("cp.async.commit_group;" ::: "memory");
        }

        const uint32_t* As = sAm + s * 4096;
        const uint32_t* Bs = sBm + s * 4096;
#pragma unroll
        for (int ksp = 0; ksp < 4; ksp++) {
            uint4 af[4];
            uint2 bf[4];
#pragma unroll
            for (int mi = 0; mi < 4; mi++)
                af[mi] = *(const uint4*)&As[(((wy * 4 + mi) * 4 + ksp) << 7) + (lane << 2)];
#pragma unroll
            for (int ni = 0; ni < 4; ni++)
                bf[ni] = *(const uint2*)&Bs[(((wx * 4 + ni) * 4 + ksp) << 6) + (lane << 1)];
#pragma unroll
            for (int mi = 0; mi < 4; mi++)
#pragma unroll
                for (int ni = 0; ni < 4; ni++)
                    MMA_F16(acc[mi][ni], af[mi].x, af[mi].y, af[mi].z, af[mi].w,
                            bf[ni].x, bf[ni].y);
        }
    }

#pragma unroll
    for (int mi = 0; mi < 4; mi++) {
        int r0 = m0 + wy * 64 + mi * 16 + gid;
#pragma unroll
        for (int ni = 0; ni < 4; ni++) {
            int feat = n0 + wx * 32 + ni * 8 + 2 * tig;
            float2 bb = *(const float2*)&bias[feat];
            if (MODE == 0) {
                int sec = feat >> 10, hm = feat & 1023;
                int h = hm >> 6, d = hm & 63;
                if (sec < 2) {
                    uint32_t* dst = (sec == 0) ? g_qh : g_kh;
                    float sc = (sec == 1) ? 0.125f : 1.0f;
                    dst[((size_t)(h * Nn + r0) << 5) + (d >> 1)] =
                        f2h2((acc[mi][ni][0] + bb.x) * sc, (acc[mi][ni][1] + bb.y) * sc);
                    dst[((size_t)(h * Nn + r0 + 8) << 5) + (d >> 1)] =
                        f2h2((acc[mi][ni][2] + bb.x) * sc, (acc[mi][ni][3] + bb.y) * sc);
                } else {
                    __half* vt = (__half*)g_vT;
                    size_t b0 = (size_t)(h * 64 + d) * 2304 + 128;
                    size_t b1 = (size_t)(h * 64 + d + 1) * 2304 + 128;
                    vt[b0 + r0]     = __float2half_rn(acc[mi][ni][0] + bb.x);
                    vt[b1 + r0]     = __float2half_rn(acc[mi][ni][1] + bb.y);
                    vt[b0 + r0 + 8] = __float2half_rn(acc[mi][ni][2] + bb.x);
                    vt[b1 + r0 + 8] = __float2half_rn(acc[mi][ni][3] + bb.y);
                }
            } else {
                float2 v0 = make_float2(acc[mi][ni][0] + bb.x, acc[mi][ni][1] + bb.y);
                float2 v1 = make_float2(acc[mi][ni][2] + bb.x, acc[mi][ni][3] + bb.y);
                *(float2*)&out[(size_t)r0 * Dd + feat] = v0;
                *(float2*)&out[(size_t)(r0 + 8) * Dd + feat] = v1;
            }
        }
    }
}

// ---------------- fused banded attention, QT=128, two halves --------------
#define QT 128
#define BND 336
#define ERWS 224
#define KWP 36         // word pitch Q/E/K rows
#define PWP 116        // word pitch P rows
#define VWP 172        // word pitch Vt rows (168 data + 4)
#define SSP2 228       // fp32 S pitch (per-half, 64 rows)
#define SQ_W (QT * KWP)                  // 4608
#define SE_W (ERWS * KWP)                // 8064
#define SP_W (64 * PWP)                  // 7424
#define SK_W (BND * KWP)                 // 12096
#define SV_W (64 * VWP)                  // 11008
#define SS_F (64 * SSP2)                 // 14592
#define ATTN_SMEM_BYTES ((SQ_W + SE_W + SP_W + SK_W + SV_W + SS_F) * 4)  // 231168

__device__ __forceinline__ void store_afrag2(int R, int C, float v0, float v1) {
    int mt = R >> 4, ks16 = C >> 4;
    int r = R & 15, c = C & 15;
    int lane = ((r & 7) << 2) + ((c & 7) >> 1);
    int reg = (r >> 3) + ((c >> 3) << 1);
    g_Ap[((((size_t)mt * 64 + ks16) << 5) + lane) * 4 + reg] = f2h2(v0, v1);
}

__global__ void __launch_bounds__(512) attn_kernel()
{
    extern __shared__ __align__(16) uint32_t smw[];
    uint32_t* sQw = smw;                             // [128][KWP]
    uint32_t* sEw = smw + SQ_W;                      // [224][KWP]
    uint32_t* sPw = smw + SQ_W + SE_W;               // [64][PWP] (per half)
    uint32_t* sKw = smw + SQ_W + SE_W + SP_W;        // [336][KWP]
    uint32_t* sVw = smw + SQ_W + SE_W + SP_W + SK_W; // [64][VWP]
    float* sS = (float*)(smw + SQ_W + SE_W + SP_W + SK_W + SV_W); // [64][SSP2]
    const uint32_t sQu = smem_u32(sQw);
    const uint32_t sEu = smem_u32(sEw);
    const uint32_t sKu = smem_u32(sKw);
    const uint32_t sVu = smem_u32(sVw);

    const int h = blockIdx.y;
    const int i0 = blockIdx.x * QT;
    const int JLO = i0 - 104;                        // even, 8-half aligned
    const int t = threadIdx.x;
    const int w = t >> 5, lane = t & 31;
    const int gid = lane >> 2, tig = lane & 3;
    const int mw = w & 3, nw = w >> 2;

    // ---- group A: Q (128 rows) + E (224 rows) ----
    for (int idx = t; idx < QT * 8; idx += 512) {
        int qi = idx >> 3, c8 = (idx & 7) << 2;
        cp16(sQu + (uint32_t)(qi * KWP + c8) * 4,
             g_qh + (((size_t)(h * Nn + i0 + qi)) << 5) + c8);
    }
    for (int idx = t; idx < ERWS * 8; idx += 512) {
        int r = idx >> 3, c8 = (idx & 7) << 2;
        cp16(sEu + (uint32_t)(r * KWP + c8) * 4,
             g_Eh + (((size_t)(h * ERWS + r)) << 5) + c8);
    }
    asm volatile("cp.async.commit_group;" ::: "memory");

    // ---- group B: K band (336 rows, zero OOB) ----
    for (int idx = t; idx < BND * 8; idx += 512) {
        int jj = idx >> 3, c8 = (idx & 7) << 2;
        int j = JLO + jj;
        if (j >= 0 && j < Nn)
            cp16(sKu + (uint32_t)(jj * KWP + c8) * 4,
                 g_kh + (((size_t)(h * Nn + j)) << 5) + c8);
        else {
            uint4 z = {0, 0, 0, 0};
            *(uint4*)&sKw[jj * KWP + c8] = z;
        }
    }
    asm volatile("cp.async.commit_group;" ::: "memory");

    // ---- group C: Vt (64 d-rows x 168 words) ----
    for (int idx = t; idx < 64 * 42; idx += 512) {
        int d = idx / 42, wc4 = (idx % 42) << 2;
        cp16(sVu + (uint32_t)(d * VWP + wc4) * 4,
             g_vT + (size_t)(h * 64 + d) * 1152 + 64 + (JLO >> 1) + wc4);
    }
    asm volatile("cp.async.commit_group;" ::: "memory");

    asm volatile("cp.async.wait_group 2;" ::: "memory");
    __syncthreads();

    for (int half = 0; half < 2; ++half) {
        const int M = half * 4 + mw;        // global m-tile index (0..7)
        const int rbase = half * 64;

        // ---- Spos = Q(half) @ E^T ----
        float pacc[7][4];
#pragma unroll
        for (int f = 0; f < 7; f++)
#pragma unroll
            for (int j = 0; j < 4; j++) pacc[f][j] = 0.f;
#pragma unroll
        for (int ks = 0; ks < 4; ks++) {
            int kb = ks * 8 + tig;
            uint32_t a0 = sQw[(rbase + mw * 16 + gid) * KWP + kb];
            uint32_t a1 = sQw[(rbase + mw * 16 + gid + 8) * KWP + kb];
            uint32_t a2 = sQw[(rbase + mw * 16 + gid) * KWP + kb + 4];
            uint32_t a3 = sQw[(rbase + mw * 16 + gid + 8) * KWP + kb + 4];
#pragma unroll
            for (int f = 0; f < 7; f++) {
                int nb = (nw * 7 + f) * 8 + gid;
                uint32_t b0 = sEw[nb * KWP + kb];
                uint32_t b1 = sEw[nb * KWP + kb + 4];
                MMA_F16(pacc[f], a0, a1, a2, a3, b0, b1);
            }
        }

        asm volatile("cp.async.wait_group 1;" ::: "memory");
        __syncthreads();

        // ---- Sqk band-restricted -> fp32 S (band-relative to 16M) ----
        {
            float acc[7][4];
#pragma unroll
            for (int f = 0; f < 7; f++)
#pragma unroll
                for (int j = 0; j < 4; j++) acc[f][j] = 0.f;
#pragma unroll
            for (int ks = 0; ks < 4; ks++) {
                int kb = ks * 8 + tig;
                uint32_t a0 = sQw[(rbase + mw * 16 + gid) * KWP + kb];
                uint32_t a1 = sQw[(rbase + mw * 16 + gid + 8) * KWP + kb];
                uint32_t a2 = sQw[(rbase + mw * 16 + gid) * KWP + kb + 4];
                uint32_t a3 = sQw[(rbase + mw * 16 + gid + 8) * KWP + kb + 4];
#pragma unroll
                for (int f = 0; f < 7; f++) {
                    int nb = (2 * M + nw * 7 + f) * 8 + gid;
                    uint32_t b0 = sKw[nb * KWP + kb];
                    uint32_t b1 = sKw[nb * KWP + kb + 4];
                    MMA_F16(acc[f], a0, a1, a2, a3, b0, b1);
                }
            }
            int r0 = mw * 16 + gid;
#pragma unroll
            for (int f = 0; f < 7; f++) {
                int col = (nw * 7 + f) * 8 + 2 * tig;
                *(float2*)&sS[r0 * SSP2 + col] = make_float2(acc[f][0], acc[f][1]);
                *(float2*)&sS[(r0 + 8) * SSP2 + col] = make_float2(acc[f][2], acc[f][3]);
            }
        }
        __syncthreads();

        // ---- merge pos into S (scalar, guarded against pitch overflow) ----
        {
            int rl0 = gid + 5, rl1 = gid + 13;
            int q0 = mw * 16 + gid, q1 = q0 + 8;
#pragma unroll
            for (int f = 0; f < 7; f++) {
                int r = (nw * 7 + f) * 8 + 2 * tig;
                if (rl0 + r + 1 < SSP2) {
                    float* p0 = &sS[q0 * SSP2 + rl0 + r];
                    p0[0] += pacc[f][0];
                    p0[1] += pacc[f][1];
                }
                if (rl1 + r + 1 < SSP2) {
                    float* p1 = &sS[q1 * SSP2 + rl1 + r];
                    p1[0] += pacc[f][2];
                    p1[1] += pacc[f][3];
                }
            }
        }
        __syncthreads();

        // ---- banded softmax (fp32), write P (fp16) into sPw ----
        {
            __half* sPh = (__half*)sPw;
            float v[4][7];
#pragma unroll
            for (int p = 0; p < 4; p++) {
                int qi = w * 4 + p;
                int ql = qi & 15;
                int i = i0 + rbase + qi;
#pragma unroll
                for (int u = 0; u < 7; u++) {
                    int r = lane + u * 32;
                    float val = -1e30f;
                    if (r < NEMB) {
                        int j = i - RAD + r;
                        if (j >= 0 && j < Nn)
                            val = sS[qi * SSP2 + ql + 5 + r];
                    }
                    v[p][u] = val;
                }
            }
            float mx[4];
#pragma unroll
            for (int p = 0; p < 4; p++) {
                mx[p] = v[p][0];
#pragma unroll
                for (int u = 1; u < 7; u++) mx[p] = fmaxf(mx[p], v[p][u]);
            }
#pragma unroll
            for (int off = 16; off; off >>= 1)
#pragma unroll
                for (int p = 0; p < 4; p++)
                    mx[p] = fmaxf(mx[p], __shfl_xor_sync(0xffffffffu, mx[p], off));
            float s[4] = {0.f, 0.f, 0.f, 0.f};
#pragma unroll
            for (int p = 0; p < 4; p++)
#pragma unroll
                for (int u = 0; u < 7; u++) {
                    v[p][u] = (v[p][u] > -1e29f) ? __expf(v[p][u] - mx[p]) : 0.f;
                    s[p] += v[p][u];
                }
#pragma unroll
            for (int off = 16; off; off >>= 1)
#pragma unroll
                for (int p = 0; p < 4; p++)
                    s[p] += __shfl_xor_sync(0xffffffffu, s[p], off);
            float inv[4];
#pragma unroll
            for (int p = 0; p < 4; p++) inv[p] = 1.f / s[p];

#pragma unroll
            for (int p = 0; p < 4; p++) {
                int qi = w * 4 + p;
#pragma unroll
                for (int u = 0; u < 4; u++) {
                    int wd = lane + u * 32;
                    if (wd < 112) sPw[qi * PWP + wd] = 0u;
                }
            }
            __syncwarp();
#pragma unroll
            for (int p = 0; p < 4; p++) {
                int qi = w * 4 + p;
                int ql = qi & 15;
#pragma unroll
                for (int u = 0; u < 7; u++) {
                    int r = lane + u * 32;
                    if (r < NEMB && v[p][u] != 0.f)
                        sPh[qi * (PWP * 2) + ql + 5 + r] =
                            __float2half_rn(v[p][u] * inv[p]);
                }
            }
        }
        asm volatile("cp.async.wait_group 0;" ::: "memory");
        __syncthreads();

        // ---- O = P @ Vt (14 k16-steps) ----
        {
            float acc[2][4];
#pragma unroll
            for (int ff = 0; ff < 2; ff++)
#pragma unroll
                for (int j = 0; j < 4; j++) acc[ff][j] = 0.f;

#pragma unroll
            for (int ks = 0; ks < 14; ks++) {
                int kb = ks * 8 + tig;
                uint32_t a0 = sPw[(mw * 16 + gid) * PWP + kb];
                uint32_t a1 = sPw[(mw * 16 + gid + 8) * PWP + kb];
                uint32_t a2 = sPw[(mw * 16 + gid) * PWP + kb + 4];
                uint32_t a3 = sPw[(mw * 16 + gid + 8) * PWP + kb + 4];
#pragma unroll
                for (int ff = 0; ff < 2; ff++) {
                    int nd = (nw * 2 + ff) * 8 + gid;
                    uint32_t b0 = sVw[nd * VWP + M * 8 + kb];
                    uint32_t b1 = sVw[nd * VWP + M * 8 + kb + 4];
                    MMA_F16(acc[ff], a0, a1, a2, a3, b0, b1);
                }
            }
            int R0 = i0 + rbase + mw * 16 + gid;
            int R1 = R0 + 8;
#pragma unroll
            for (int ff = 0; ff < 2; ff++) {
                int C = h * 64 + (nw * 2 + ff) * 8 + 2 * tig;
                store_afrag2(R0, C, acc[ff][0], acc[ff][1]);
                store_afrag2(R1, C, acc[ff][2], acc[ff][3]);
            }
        }
    }
}

// ---------------- launcher ------------------------------------------------
extern "C" void kernel_launch(void* const* d_in, const int* in_sizes, int n_in,
                              void* d_out, int out_size)
{
    (void)in_sizes; (void)n_in; (void)out_size;
    const float* x      = (const float*)d_in[0];
    const float* qkv_w  = (const float*)d_in[1];
    const float* qkv_b  = (const float*)d_in[2];
    const float* proj_w = (const float*)d_in[3];
    const float* proj_b = (const float*)d_in[4];
    const float* rel    = (const float*)d_in[5];
    float* out = (float*)d_out;

    cudaFuncSetAttribute(mma_gemm<0>, cudaFuncAttributeMaxDynamicSharedMemorySize,
                         GEMM_SMEM_BYTES);
    cudaFuncSetAttribute(mma_gemm<1>, cudaFuncAttributeMaxDynamicSharedMemorySize,
                         GEMM_SMEM_BYTES);
    cudaFuncSetAttribute(attn_kernel, cudaFuncAttributeMaxDynamicSharedMemorySize,
                         ATTN_SMEM_BYTES);

    // 1) all packs in one launch (A(x), B(qkv_w), E, B2(proj_w))
    pack_all<<<5568, 256>>>(x, qkv_w, proj_w, rel);
    // 2) QKV GEMM (fp16, BK=64): emit fp16 q/k rows + transposed fp16 V
    mma_gemm<0><<<dim3(3 * Dd / 128, Nn / 128), 256, GEMM_SMEM_BYTES>>>(qkv_b,
                                                                        nullptr, Dd);
    // 3) fused pos + banded attention (QT=128, fp16) -> g_Ap
    attn_kernel<<<dim3(Nn / QT, Hh), 512, ATTN_SMEM_BYTES>>>();
    // 4) output projection (fp16, BK=64) -> d_out
    mma_gemm<1><<<dim3(Dd / 128, Nn / 128), 256, GEMM_SMEM_BYTES>>>(proj_b, out, Dd);
}